// round 15
// baseline (speedup 1.0000x reference)
#include <cuda_runtime.h>
#include <cuda_bf16.h>
#include <cstdint>
#include <cstddef>

using bf16 = __nv_bfloat16;

#define DI __device__ __forceinline__

// ---------------- constants ----------------
static constexpr int Bb = 32;
static constexpr int Tt = 48;

// ---------------- scratch layout ----------------
constexpr size_t O_ENC_H   = 0;
constexpr size_t O_ENC_L   = O_ENC_H   + (size_t)2048*1024*2;
constexpr size_t O_ATTNS   = O_ENC_L   + (size_t)2048*1024*2;
constexpr size_t O_WPROJ_H = O_ATTNS   + (size_t)2048*1024*4;
constexpr size_t O_WPROJ_L = O_WPROJ_H + (size_t)1024*1024*2;
constexpr size_t O_WWORD_H = O_WPROJ_L + (size_t)1024*1024*2;
constexpr size_t O_WWORD_L = O_WWORD_H + (size_t)4096*512*2;
constexpr size_t O_WCAT_H  = O_WWORD_L + (size_t)4096*512*2;
constexpr size_t O_WCAT_L  = O_WCAT_H  + (size_t)4096*2048*2;
constexpr size_t O_W1_H    = O_WCAT_L  + (size_t)4096*2048*2;
constexpr size_t O_W1_L    = O_W1_H    + (size_t)4096*1024*2;
constexpr size_t O_WCOMB_H = O_W1_L    + (size_t)4096*1024*2;
constexpr size_t O_WCOMB_L = O_WCOMB_H + (size_t)1024*2048*2;
constexpr size_t O_WOUT_H  = O_WCOMB_L + (size_t)1024*2048*2;
constexpr size_t O_WOUT_L  = O_WOUT_H  + (size_t)32000*1024*2;
constexpr size_t O_BIAS0   = O_WOUT_L  + (size_t)32000*1024*2;
constexpr size_t O_BIAS1   = O_BIAS0   + (size_t)4096*4;
constexpr size_t O_AEMB_H  = O_BIAS1   + (size_t)4096*4;
constexpr size_t O_AEMB_L  = O_AEMB_H  + (size_t)1536*512*2;
constexpr size_t O_GWORD   = O_AEMB_L  + (size_t)1536*512*2;
constexpr size_t O_X_H     = O_GWORD   + (size_t)1536*4096*4;
constexpr size_t O_X_L     = O_X_H     + (size_t)32*2048*2;
constexpr size_t O_Y_H     = O_X_L     + (size_t)32*2048*2;
constexpr size_t O_Y_L     = O_Y_H     + (size_t)32*2048*2;
constexpr size_t O_HMID_H  = O_Y_L     + (size_t)32*2048*2;
constexpr size_t O_HMID_L  = O_HMID_H  + (size_t)32*1024*2;
constexpr size_t O_HF32    = O_HMID_L  + (size_t)32*1024*2;
constexpr size_t O_CPREV   = O_HF32    + (size_t)32*1024*4;
constexpr size_t O_CMID    = O_CPREV   + (size_t)32*1024*4;
constexpr size_t O_AV_H    = O_CMID    + (size_t)32*1024*4;
constexpr size_t O_AV_L    = O_AV_H    + (size_t)1536*1024*2;
constexpr size_t SCRATCH_BYTES = O_AV_L + (size_t)1536*1024*2;

__device__ __align__(1024) unsigned char g_scratch[SCRATCH_BYTES];

// ---------------- 32-block barrier (padded, self-resetting; R6/R7-validated) ----
__device__ __align__(128) unsigned g_b32_count = 0;
__device__ __align__(128) unsigned g_b32_gen   = 0;

DI void grid_barrier32(){
    __syncthreads();
    if (threadIdx.x == 0){
        volatile unsigned* vgen = &g_b32_gen;
        unsigned seen = *vgen;               // read BEFORE arriving
        __threadfence();                     // release our writes
        unsigned a = atomicAdd(&g_b32_count, 1u);
        if (a == 31u){
            *(volatile unsigned*)&g_b32_count = 0u;
            __threadfence();
            atomicAdd(&g_b32_gen, 1u);       // release
        } else {
            while (*vgen == seen) { }
        }
        __threadfence();                     // acquire
    }
    __syncthreads();
}

// ---------------- helpers ----------------
DI float sigmoidf_(float x){ return 1.0f/(1.0f+expf(-x)); }

DI void split_store(float v, bf16* ph, bf16* pl){
    bf16 h = __float2bfloat16(v);
    *ph = h;
    *pl = __float2bfloat16(v - __bfloat162float(h));
}

DI void split_q(float4 v, __nv_bfloat162* h2, __nv_bfloat162* l2, size_t i){
    bf16 h0 = __float2bfloat16(v.x), h1 = __float2bfloat16(v.y);
    bf16 h2v = __float2bfloat16(v.z), h3 = __float2bfloat16(v.w);
    bf16 l0 = __float2bfloat16(v.x - __bfloat162float(h0));
    bf16 l1 = __float2bfloat16(v.y - __bfloat162float(h1));
    bf16 l2v = __float2bfloat16(v.z - __bfloat162float(h2v));
    bf16 l3 = __float2bfloat16(v.w - __bfloat162float(h3));
    h2[i*2]   = __nv_bfloat162(h0, h1);
    h2[i*2+1] = __nv_bfloat162(h2v, h3);
    l2[i*2]   = __nv_bfloat162(l0, l1);
    l2[i*2+1] = __nv_bfloat162(l2v, l3);
}

DI void cpasync16(void* sdst, const void* gsrc){
    uint32_t sa = (uint32_t)__cvta_generic_to_shared(sdst);
    asm volatile("cp.async.cg.shared.global [%0], [%1], 16;\n" :: "r"(sa), "l"(gsrc));
}
DI void cpcommit(){ asm volatile("cp.async.commit_group;\n"); }
template<int N> DI void cpwait(){ asm volatile("cp.async.wait_group %0;\n" :: "n"(N)); }

DI void mma_bf16(float* c, const uint32_t* a, const uint32_t* b){
    asm volatile(
        "mma.sync.aligned.m16n8k16.row.col.f32.bf16.bf16.f32 "
        "{%0,%1,%2,%3}, {%4,%5,%6,%7}, {%8,%9}, {%0,%1,%2,%3};\n"
        : "+f"(c[0]), "+f"(c[1]), "+f"(c[2]), "+f"(c[3])
        : "r"(a[0]), "r"(a[1]), "r"(a[2]), "r"(a[3]), "r"(b[0]), "r"(b[1]));
}

// ---------------- prep kernels (vectorized) ----------------
__global__ void k_split_plain4(const float4* __restrict__ src, __nv_bfloat162* __restrict__ h2,
                               __nv_bfloat162* __restrict__ l2, size_t n4){
    for (size_t i = (size_t)blockIdx.x*blockDim.x + threadIdx.x; i < n4;
         i += (size_t)gridDim.x*blockDim.x)
        split_q(src[i], h2, l2, i);
}

// enc [b*64+s][k] <- src_encodings[s][b][k]  (float4 over k)
__global__ void k_split_enc4(const float4* __restrict__ src4, __nv_bfloat162* __restrict__ h2,
                             __nv_bfloat162* __restrict__ l2){
    size_t n4 = (size_t)2048*256;
    for (size_t i = (size_t)blockIdx.x*blockDim.x + threadIdx.x; i < n4;
         i += (size_t)gridDim.x*blockDim.x){
        int r = (int)(i >> 8), kq = (int)(i & 255);
        int b = r >> 6, s = r & 63;
        split_q(src4[(size_t)(s*Bb + b)*256 + kq], h2, l2, i);
    }
}

// permuted row r = 4*ch + gate ; source row = gate*1024 + ch
DI int perm_src_row(int r){ return (r & 3)*1024 + (r >> 2); }

__global__ void k_build_wword4(const float4* __restrict__ W4, __nv_bfloat162* __restrict__ h2,
                               __nv_bfloat162* __restrict__ l2){
    size_t n4 = (size_t)4096*128;
    for (size_t i = (size_t)blockIdx.x*blockDim.x + threadIdx.x; i < n4;
         i += (size_t)gridDim.x*blockDim.x){
        int r = (int)(i >> 7), kq = (int)(i & 127);
        split_q(W4[(size_t)perm_src_row(r)*384 + kq], h2, l2, i);
    }
}

__global__ void k_build_wcat4(const float4* __restrict__ Wih0_4, const float4* __restrict__ Whh0_4,
                              __nv_bfloat162* __restrict__ h2, __nv_bfloat162* __restrict__ l2){
    size_t n4 = (size_t)4096*512;
    for (size_t i = (size_t)blockIdx.x*blockDim.x + threadIdx.x; i < n4;
         i += (size_t)gridDim.x*blockDim.x){
        int r = (int)(i >> 9), kq = (int)(i & 511);
        int sr = perm_src_row(r);
        float4 v = (kq < 256) ? Wih0_4[(size_t)sr*384 + 128 + kq]
                              : Whh0_4[(size_t)sr*256 + (kq - 256)];
        split_q(v, h2, l2, i);
    }
}

__global__ void k_build_w1_4(const float4* __restrict__ Wih1_4, const float4* __restrict__ Whh1_4,
                             __nv_bfloat162* __restrict__ h2, __nv_bfloat162* __restrict__ l2){
    size_t n4 = (size_t)4096*256;
    for (size_t i = (size_t)blockIdx.x*blockDim.x + threadIdx.x; i < n4;
         i += (size_t)gridDim.x*blockDim.x){
        int r = (int)(i >> 8), kq = (int)(i & 255);
        int sr = perm_src_row(r);
        float4 a = Wih1_4[(size_t)sr*256 + kq];
        float4 b = Whh1_4[(size_t)sr*256 + kq];
        float4 v = make_float4(a.x+b.x, a.y+b.y, a.z+b.z, a.w+b.w);
        split_q(v, h2, l2, i);
    }
}

__global__ void k_build_bias(const float* __restrict__ bi0, const float* __restrict__ bh0,
                             const float* __restrict__ bi1, const float* __restrict__ bh1,
                             float* __restrict__ o0, float* __restrict__ o1){
    int r = blockIdx.x*blockDim.x + threadIdx.x;
    if (r < 4096){
        int sr = perm_src_row(r);
        o0[r] = bi0[sr] + bh0[sr];
        o1[r] = bi1[sr] + bh1[sr];
    }
}

__global__ void k_gather_emb4(const float4* __restrict__ emb4, const int* __restrict__ tgt,
                              __nv_bfloat162* __restrict__ h2, __nv_bfloat162* __restrict__ l2){
    size_t n4 = (size_t)1536*128;
    for (size_t i = (size_t)blockIdx.x*blockDim.x + threadIdx.x; i < n4;
         i += (size_t)gridDim.x*blockDim.x){
        int m = (int)(i >> 7), kq = (int)(i & 127);
        split_q(emb4[(size_t)tgt[m]*128 + kq], h2, l2, i);
    }
}

__global__ void k_init_state(const float* __restrict__ h0, const float* __restrict__ c0,
                             float* __restrict__ cprev, bf16* __restrict__ Xh,
                             bf16* __restrict__ Xl){
    int i = blockIdx.x*blockDim.x + threadIdx.x;
    if (i < 32*1024){
        int row = i >> 10, k = i & 1023;
        cprev[i] = c0[i];
        bf16 z = __float2bfloat16(0.0f);
        Xh[row*2048 + k] = z;
        Xl[row*2048 + k] = z;
        split_store(h0[i], Xh + row*2048 + 1024 + k, Xl + row*2048 + 1024 + k);
    }
}

// ---------------- 3-pass split-bf16 GEMM (PDL, trigger at end) ----------------
// C[M,N] = A[M,K] * B[N,K]^T  with A ~ Ah+Al, B ~ Bh+Bl (3 mma passes).
// epi: 0=store, 1=store+bias, 2=LSTM cell (interleaved gates)
template<int BM, int BN, int BK, int WM, int WN, int STAGES>
__global__ void __launch_bounds__(32*(BM/WM)*(BN/WN))
gemm3(const bf16* __restrict__ Ah, const bf16* __restrict__ Al, int lda,
      const bf16* __restrict__ Bh, const bf16* __restrict__ Bl, int ldb,
      float* __restrict__ C, int ldc,
      int M, int N, int K, int epi,
      const float* __restrict__ addend,
      const float* __restrict__ bias,
      const float* __restrict__ cin, float* __restrict__ cout,
      bf16* __restrict__ h1h, bf16* __restrict__ h1l, int h1ld,
      bf16* __restrict__ h2h, bf16* __restrict__ h2l, int h2ld,
      float* __restrict__ hf32)
{
    constexpr int WARPS_M = BM/WM, WARPS_N = BN/WN;
    constexpr int THREADS = 32*WARPS_M*WARPS_N;
    constexpr int MF = WM/16, NF = WN/8;
    constexpr int BKP = BK + 8;
    constexpr int WRD = BKP/2;
    constexpr int CH  = BK/8;
    constexpr int ASZ = BM*BKP, BSZ = BN*BKP;
    constexpr int STG = 2*ASZ + 2*BSZ;
    extern __shared__ bf16 smem[];

    const int tid = threadIdx.x, wid = tid >> 5, lane = tid & 31;
    const int wm = wid / WARPS_N, wn = wid % WARPS_N;
    const int g = lane >> 2, t = lane & 3;
    const int bm0 = blockIdx.x*BM, bn0 = blockIdx.y*BN;

    float acc[MF][NF][4];
    #pragma unroll
    for (int a = 0; a < MF; a++)
        #pragma unroll
        for (int b = 0; b < NF; b++)
            #pragma unroll
            for (int c = 0; c < 4; c++) acc[a][b][c] = 0.f;

    const int KT = K/BK;

    auto loadB = [&](int kt, int st){
        bf16* s = smem + st*STG;
        int k0 = kt*BK;
        for (int c = tid; c < BN*CH; c += THREADS){
            int r = c/CH, cc = c%CH;
            size_t go = (size_t)(bn0 + r)*ldb + k0 + cc*8;
            cpasync16(s + 2*ASZ + r*BKP + cc*8, Bh + go);
            cpasync16(s + 2*ASZ + BSZ + r*BKP + cc*8, Bl + go);
        }
    };
    auto loadA = [&](int kt, int st){
        bf16* s = smem + st*STG;
        int k0 = kt*BK;
        for (int c = tid; c < BM*CH; c += THREADS){
            int r = c/CH, cc = c%CH;
            size_t go = (size_t)(bm0 + r)*lda + k0 + cc*8;
            cpasync16(s + r*BKP + cc*8, Ah + go);
            cpasync16(s + ASZ + r*BKP + cc*8, Al + go);
        }
    };

    // Weight (B) prefetch overlaps the predecessor tail; sync before touching A.
    #pragma unroll
    for (int s = 0; s < STAGES-1; s++) loadB(s, s);
    cudaGridDependencySynchronize();
    loadA(0, 0); cpcommit();
    #pragma unroll
    for (int s = 1; s < STAGES-1; s++){ loadA(s, s); cpcommit(); }

    for (int kt = 0; kt < KT; kt++){
        cpwait<STAGES-2>();
        __syncthreads();
        int nstage = kt + STAGES - 1;
        if (nstage < KT){ loadB(nstage, nstage % STAGES); loadA(nstage, nstage % STAGES); }
        cpcommit();

        const bf16* s = smem + (kt % STAGES)*STG;
        const uint32_t* sAh = (const uint32_t*)s;
        const uint32_t* sAl = (const uint32_t*)(s + ASZ);
        const uint32_t* sBh = (const uint32_t*)(s + 2*ASZ);
        const uint32_t* sBl = (const uint32_t*)(s + 2*ASZ + BSZ);
        #pragma unroll
        for (int ks = 0; ks < BK/16; ks++){
            uint32_t af[MF][4], alf[MF][4], bhf[NF][2], blf[NF][2];
            #pragma unroll
            for (int mf = 0; mf < MF; mf++){
                int r0 = wm*WM + mf*16;
                int i0 = (r0 + g)*WRD + ks*8 + t;
                int i1 = (r0 + g + 8)*WRD + ks*8 + t;
                af[mf][0] = sAh[i0];   af[mf][1] = sAh[i1];
                af[mf][2] = sAh[i0+4]; af[mf][3] = sAh[i1+4];
                alf[mf][0] = sAl[i0];   alf[mf][1] = sAl[i1];
                alf[mf][2] = sAl[i0+4]; alf[mf][3] = sAl[i1+4];
            }
            #pragma unroll
            for (int nf = 0; nf < NF; nf++){
                int cb = wn*WN + nf*8 + g;
                int i0 = cb*WRD + ks*8 + t;
                bhf[nf][0] = sBh[i0]; bhf[nf][1] = sBh[i0+4];
                blf[nf][0] = sBl[i0]; blf[nf][1] = sBl[i0+4];
            }
            #pragma unroll
            for (int mf = 0; mf < MF; mf++)
                #pragma unroll
                for (int nf = 0; nf < NF; nf++){
                    mma_bf16(acc[mf][nf], af[mf],  bhf[nf]);
                    mma_bf16(acc[mf][nf], alf[mf], bhf[nf]);
                    mma_bf16(acc[mf][nf], af[mf],  blf[nf]);
                }
        }
        __syncthreads();
    }

    // epilogue
    #pragma unroll
    for (int mf = 0; mf < MF; mf++){
        #pragma unroll
        for (int nf = 0; nf < NF; nf++){
            #pragma unroll
            for (int half = 0; half < 2; half++){
                int row = bm0 + wm*WM + mf*16 + g + half*8;
                int col = bn0 + wn*WN + nf*8 + 2*t;
                float v0 = acc[mf][nf][half*2 + 0];
                float v1 = acc[mf][nf][half*2 + 1];
                if (epi <= 1){
                    if (epi == 1){ v0 += bias[col]; v1 += bias[col+1]; }
                    C[(size_t)row*ldc + col]     = v0;
                    C[(size_t)row*ldc + col + 1] = v1;
                } else {
                    if (addend){ v0 += addend[(size_t)row*N + col];
                                 v1 += addend[(size_t)row*N + col + 1]; }
                    if (bias){ v0 += bias[col]; v1 += bias[col+1]; }
                    float w0 = __shfl_xor_sync(0xffffffffu, v0, 1);
                    float w1 = __shfl_xor_sync(0xffffffffu, v1, 1);
                    if ((t & 1) == 0){
                        // even lanes hold (i,f); partner holds (g,o)
                        float ig = sigmoidf_(v0), fg = sigmoidf_(v1);
                        float gg = tanhf(w0),    og = sigmoidf_(w1);
                        int ch = col >> 2;
                        float cn = fg*cin[row*1024 + ch] + ig*gg;
                        float hn = og*tanhf(cn);
                        cout[row*1024 + ch] = cn;
                        bf16 hh = __float2bfloat16(hn);
                        bf16 hl = __float2bfloat16(hn - __bfloat162float(hh));
                        h1h[row*h1ld + ch] = hh;
                        h1l[row*h1ld + ch] = hl;
                        if (h2h){ h2h[row*h2ld + ch] = hh; h2l[row*h2ld + ch] = hl; }
                        if (hf32) hf32[row*1024 + ch] = hn;
                    }
                }
            }
        }
    }
    cudaTriggerProgrammaticLaunchCompletion();
}

// ---------------- fused attention + combine (32 blocks x 512 threads) --------------
// Phase 1: attention for batch b = blockIdx.x (identical math to R11's k_attention).
// Barrier (all Y rows written). Phase 2: combine tile BN=32 cols [32b,32b+32),
// BM=32 rows, K=2048, BK=128, 3-stage cp.async (warps 0-7 do mma; all load/sync).
__global__ void __launch_bounds__(512)
k_attn_comb(const float* __restrict__ attnS, const float* __restrict__ hf,
            const float* __restrict__ src,
            bf16* __restrict__ Yh, bf16* __restrict__ Yl,
            const bf16* __restrict__ WcombH, const bf16* __restrict__ WcombL,
            bf16* __restrict__ XH, bf16* __restrict__ XL,
            bf16* __restrict__ AVH, bf16* __restrict__ AVL, int r0)
{
    constexpr int BK = 128, BKP = BK + 8, WRD = BKP/2;
    constexpr int ASZ = 32*BKP, BSZ = 32*BKP, STG = 2*ASZ + 2*BSZ;  // elems
    extern __shared__ bf16 smem[];
    __shared__ float sh[1024];
    __shared__ float salpha[64];
    __shared__ float sinv;

    const int tid = threadIdx.x, w = tid >> 5, lane = tid & 31;
    const int b = blockIdx.x;
    const int bn0 = b*32;

    auto loadB = [&](int kt, int st){
        bf16* s = smem + st*STG;
        int r = tid >> 4, c = tid & 15;            // 32 rows x 16 chunks = 512
        size_t go = (size_t)(bn0 + r)*2048 + kt*BK + c*8;
        cpasync16(s + 2*ASZ + r*BKP + c*8, WcombH + go);
        cpasync16(s + 2*ASZ + BSZ + r*BKP + c*8, WcombL + go);
    };
    auto loadA = [&](int kt, int st){
        bf16* s = smem + st*STG;
        int r = tid >> 4, c = tid & 15;
        size_t go = (size_t)r*2048 + kt*BK + c*8;
        cpasync16(s + r*BKP + c*8, Yh + go);
        cpasync16(s + ASZ + r*BKP + c*8, Yl + go);
    };

    cudaGridDependencySynchronize();
    // Prefetch step-independent Wcomb stages 0,1 (uncommitted; bundled with A0).
    loadB(0, 0); loadB(1, 1);

    // ---- phase 1: attention (512 threads, identical to validated kernel) ----
    for (int i = tid; i < 1024; i += 512) sh[i] = hf[b*1024 + i];
    __syncthreads();

    #pragma unroll
    for (int j = 0; j < 4; j++){
        int s = w + 16*j;
        const float* row = attnS + (size_t)(b*64 + s)*1024;
        float acc = 0.f;
        #pragma unroll 8
        for (int k = lane; k < 1024; k += 32) acc += row[k]*sh[k];
        #pragma unroll
        for (int o = 16; o > 0; o >>= 1) acc += __shfl_xor_sync(0xffffffffu, acc, o);
        if (lane == 0) salpha[s] = acc;
    }
    __syncthreads();
    if (w == 0){
        float a0 = salpha[lane], a1 = salpha[lane + 32];
        float m = fmaxf(a0, a1);
        #pragma unroll
        for (int o = 16; o > 0; o >>= 1) m = fmaxf(m, __shfl_xor_sync(0xffffffffu, m, o));
        float e0 = expf(a0 - m), e1 = expf(a1 - m);
        salpha[lane] = e0; salpha[lane + 32] = e1;
        float su = e0 + e1;
        #pragma unroll
        for (int o = 16; o > 0; o >>= 1) su += __shfl_xor_sync(0xffffffffu, su, o);
        if (lane == 0) sinv = 1.0f/su;
    }
    __syncthreads();
    float inv = sinv;
    for (int e = tid; e < 1024; e += 512){
        float acc = 0.f;
        #pragma unroll 16
        for (int s = 0; s < 64; s++)
            acc += salpha[s]*src[((size_t)(s*Bb + b))*1024 + e];
        acc *= inv;
        split_store(acc, Yh + b*2048 + 1024 + e, Yl + b*2048 + 1024 + e);
    }

    // ---- barrier: all batches' Y complete ----
    grid_barrier32();

    // ---- phase 2: combine GEMM (BM=32, BN=32, K=2048, KT=16, 3 stages) ----
    loadA(0, 0); cpcommit();                 // group0 = {B0, B1, A0}
    loadA(1, 1); cpcommit();                 // group1 = {A1}

    const int wm = (w & 7) >> 2, wn = w & 3; // warps 0-7: 2x4 (WM=16, WN=8)
    const int g = lane >> 2, t = lane & 3;
    const bool domma = (w < 8);
    float acc[4] = {0.f, 0.f, 0.f, 0.f};

    for (int kt = 0; kt < 16; kt++){
        cpwait<1>();
        __syncthreads();
        int nst = kt + 2;
        if (nst < 16){ loadB(nst, nst % 3); loadA(nst, nst % 3); }
        cpcommit();

        if (domma){
            const bf16* s = smem + (kt % 3)*STG;
            const uint32_t* sAh = (const uint32_t*)s;
            const uint32_t* sAl = (const uint32_t*)(s + ASZ);
            const uint32_t* sBh = (const uint32_t*)(s + 2*ASZ);
            const uint32_t* sBl = (const uint32_t*)(s + 2*ASZ + BSZ);
            #pragma unroll
            for (int ks = 0; ks < 8; ks++){
                uint32_t af[4], alf[4], bhf[2], blf[2];
                int r0i = wm*16;
                int i0 = (r0i + g)*WRD + ks*8 + t;
                int i1 = (r0i + g + 8)*WRD + ks*8 + t;
                af[0] = sAh[i0];   af[1] = sAh[i1];
                af[2] = sAh[i0+4]; af[3] = sAh[i1+4];
                alf[0] = sAl[i0];   alf[1] = sAl[i1];
                alf[2] = sAl[i0+4]; alf[3] = sAl[i1+4];
                int cb = wn*8 + g;
                int j0 = cb*WRD + ks*8 + t;
                bhf[0] = sBh[j0]; bhf[1] = sBh[j0+4];
                blf[0] = sBl[j0]; blf[1] = sBl[j0+4];
                mma_bf16(acc, af,  bhf);
                mma_bf16(acc, alf, bhf);
                mma_bf16(acc, af,  blf);
            }
        }
        __syncthreads();
    }

    if (domma){
        #pragma unroll
        for (int half = 0; half < 2; half++){
            int row = wm*16 + g + half*8;
            int col = bn0 + wn*8 + 2*t;
            float a0 = tanhf(acc[half*2 + 0]);
            float a1 = tanhf(acc[half*2 + 1]);
            bf16 p0 = __float2bfloat16(a0);
            bf16 q0 = __float2bfloat16(a0 - __bfloat162float(p0));
            bf16 p1 = __float2bfloat16(a1);
            bf16 q1 = __float2bfloat16(a1 - __bfloat162float(p1));
            XH[row*2048 + col]   = p0; XL[row*2048 + col]   = q0;
            XH[row*2048 + col+1] = p1; XL[row*2048 + col+1] = q1;
            AVH[(size_t)(r0+row)*1024 + col]   = p0;
            AVL[(size_t)(r0+row)*1024 + col]   = q0;
            AVH[(size_t)(r0+row)*1024 + col+1] = p1;
            AVL[(size_t)(r0+row)*1024 + col+1] = q1;
        }
    }
    cudaTriggerProgrammaticLaunchCompletion();
}

// ---------------- host launch ----------------
static constexpr int SM_L = 2*(2*128+2*128)*(32+8)*2;    // 81920 (2 blocks/SM)
static constexpr int SM_G = 3*(2*32+2*32)*(128+8)*2;     // 104448 (BK=128 gates)
static constexpr int SM_F = 3*(2*32+2*32)*(128+8)*2;     // 104448 (fused combine)

template<typename F, typename... Args>
static void launch_pdl(F f, dim3 g, dim3 b, size_t sm, Args... args){
    cudaLaunchConfig_t cfg = {};
    cfg.gridDim = g; cfg.blockDim = b; cfg.dynamicSmemBytes = sm; cfg.stream = 0;
    cudaLaunchAttribute at[1];
    at[0].id = cudaLaunchAttributeProgrammaticStreamSerialization;
    at[0].val.programmaticStreamSerializationAllowed = 1;
    cfg.attrs = at; cfg.numAttrs = 1;
    cudaLaunchKernelEx(&cfg, f, args...);
}

extern "C" void kernel_launch(void* const* d_in, const int* in_sizes, int n_in,
                              void* d_out, int out_size){
    const float* src   = (const float*)d_in[0];
    const float* h0    = (const float*)d_in[1];
    const float* c0    = (const float*)d_in[2];
    const float* emb   = (const float*)d_in[3];
    const float* Wproj = (const float*)d_in[4];
    const float* Wcomb = (const float*)d_in[5];
    const float* Wout  = (const float*)d_in[6];
    const float* Wih0  = (const float*)d_in[7];
    const float* Whh0  = (const float*)d_in[8];
    const float* bih0  = (const float*)d_in[9];
    const float* bhh0  = (const float*)d_in[10];
    const float* Wih1  = (const float*)d_in[11];
    const float* Whh1  = (const float*)d_in[12];
    const float* bih1  = (const float*)d_in[13];
    const float* bhh1  = (const float*)d_in[14];
    const int*   tgt   = (const int*)d_in[15];
    float* out = (float*)d_out;

    void* basep = nullptr;
    cudaGetSymbolAddress(&basep, g_scratch);
    unsigned char* base = (unsigned char*)basep;

    bf16*  encH   = (bf16*)(base + O_ENC_H);
    bf16*  encL   = (bf16*)(base + O_ENC_L);
    float* attnS  = (float*)(base + O_ATTNS);
    bf16*  WprojH = (bf16*)(base + O_WPROJ_H);
    bf16*  WprojL = (bf16*)(base + O_WPROJ_L);
    bf16*  WwordH = (bf16*)(base + O_WWORD_H);
    bf16*  WwordL = (bf16*)(base + O_WWORD_L);
    bf16*  WcatH  = (bf16*)(base + O_WCAT_H);
    bf16*  WcatL  = (bf16*)(base + O_WCAT_L);
    bf16*  W1H    = (bf16*)(base + O_W1_H);
    bf16*  W1L    = (bf16*)(base + O_W1_L);
    bf16*  WcombH = (bf16*)(base + O_WCOMB_H);
    bf16*  WcombL = (bf16*)(base + O_WCOMB_L);
    bf16*  WoutH  = (bf16*)(base + O_WOUT_H);
    bf16*  WoutL  = (bf16*)(base + O_WOUT_L);
    float* bias0  = (float*)(base + O_BIAS0);
    float* bias1  = (float*)(base + O_BIAS1);
    bf16*  AembH  = (bf16*)(base + O_AEMB_H);
    bf16*  AembL  = (bf16*)(base + O_AEMB_L);
    float* Gword  = (float*)(base + O_GWORD);
    bf16*  XH     = (bf16*)(base + O_X_H);
    bf16*  XL     = (bf16*)(base + O_X_L);
    bf16*  YH     = (bf16*)(base + O_Y_H);
    bf16*  YL     = (bf16*)(base + O_Y_L);
    bf16*  HmidH  = (bf16*)(base + O_HMID_H);
    bf16*  HmidL  = (bf16*)(base + O_HMID_L);
    float* hf32   = (float*)(base + O_HF32);
    float* cprev  = (float*)(base + O_CPREV);
    float* cmid   = (float*)(base + O_CMID);
    bf16*  AVH    = (bf16*)(base + O_AV_H);
    bf16*  AVL    = (bf16*)(base + O_AV_L);

    cudaFuncSetAttribute((const void*)gemm3<128,128,32,64,32,2>,
                         cudaFuncAttributeMaxDynamicSharedMemorySize, SM_L);
    cudaFuncSetAttribute((const void*)gemm3<32,32,128,16,8,3>,
                         cudaFuncAttributeMaxDynamicSharedMemorySize, SM_G);
    cudaFuncSetAttribute((const void*)k_attn_comb,
                         cudaFuncAttributeMaxDynamicSharedMemorySize, SM_F);

    // ---- setup (vectorized splits/builders) ----
    k_split_enc4<<<2048,256>>>((const float4*)src, (__nv_bfloat162*)encH,
                               (__nv_bfloat162*)encL);
    k_split_plain4<<<2048,256>>>((const float4*)Wproj, (__nv_bfloat162*)WprojH,
                                 (__nv_bfloat162*)WprojL, (size_t)1024*1024/4);
    k_split_plain4<<<4096,256>>>((const float4*)Wcomb, (__nv_bfloat162*)WcombH,
                                 (__nv_bfloat162*)WcombL, (size_t)1024*2048/4);
    k_split_plain4<<<8192,256>>>((const float4*)Wout, (__nv_bfloat162*)WoutH,
                                 (__nv_bfloat162*)WoutL, (size_t)32000*1024/4);
    k_build_wword4<<<2048,256>>>((const float4*)Wih0, (__nv_bfloat162*)WwordH,
                                 (__nv_bfloat162*)WwordL);
    k_build_wcat4<<<4096,256>>>((const float4*)Wih0, (const float4*)Whh0,
                                (__nv_bfloat162*)WcatH, (__nv_bfloat162*)WcatL);
    k_build_w1_4<<<2048,256>>>((const float4*)Wih1, (const float4*)Whh1,
                               (__nv_bfloat162*)W1H, (__nv_bfloat162*)W1L);
    k_build_bias<<<16,256>>>(bih0, bhh0, bih1, bhh1, bias0, bias1);
    k_gather_emb4<<<1024,256>>>((const float4*)emb, tgt,
                                (__nv_bfloat162*)AembH, (__nv_bfloat162*)AembL);
    k_init_state<<<128,256>>>(h0, c0, cprev, XH, XL);

    // attn_scores = enc @ Wproj^T : [2048,1024]
    launch_pdl(gemm3<128,128,32,64,32,2>, dim3(16,8), dim3(256), (size_t)SM_L,
        (const bf16*)encH, (const bf16*)encL, 1024,
        (const bf16*)WprojH, (const bf16*)WprojL, 1024,
        attnS, 1024, 2048, 1024, 1024, 0,
        (const float*)nullptr, (const float*)nullptr,
        (const float*)nullptr, (float*)nullptr,
        (bf16*)nullptr, (bf16*)nullptr, 0,
        (bf16*)nullptr, (bf16*)nullptr, 0, (float*)nullptr);

    // G_word = emb_gathered @ Wword^T + bias0 : [1536,4096] (permuted gates)
    launch_pdl(gemm3<128,128,32,64,32,2>, dim3(12,32), dim3(256), (size_t)SM_L,
        (const bf16*)AembH, (const bf16*)AembL, 512,
        (const bf16*)WwordH, (const bf16*)WwordL, 512,
        Gword, 4096, 1536, 4096, 512, 1,
        (const float*)nullptr, (const float*)bias0,
        (const float*)nullptr, (float*)nullptr,
        (bf16*)nullptr, (bf16*)nullptr, 0,
        (bf16*)nullptr, (bf16*)nullptr, 0, (float*)nullptr);

    // ---- sequential decode loop: 3 kernels per step ----
    for (int t = 0; t < Tt; t++){
        launch_pdl(gemm3<32,32,128,16,8,3>, dim3(1,128), dim3(256), (size_t)SM_G,
            (const bf16*)XH, (const bf16*)XL, 2048,
            (const bf16*)WcatH, (const bf16*)WcatL, 2048,
            (float*)nullptr, 0, 32, 4096, 2048, 2,
            (const float*)(Gword + (size_t)t*32*4096), (const float*)nullptr,
            (const float*)cprev, cmid,
            HmidH, HmidL, 1024,
            (bf16*)nullptr, (bf16*)nullptr, 0, (float*)nullptr);

        launch_pdl(gemm3<32,32,128,16,8,3>, dim3(1,128), dim3(256), (size_t)SM_G,
            (const bf16*)HmidH, (const bf16*)HmidL, 1024,
            (const bf16*)W1H, (const bf16*)W1L, 1024,
            (float*)nullptr, 0, 32, 4096, 1024, 2,
            (const float*)nullptr, (const float*)bias1,
            (const float*)cmid, cprev,
            YH, YL, 2048,
            XH + 1024, XL + 1024, 2048, hf32);

        // fused attention + combine (32 blocks x 512 thr, internal 32-blk barrier)
        launch_pdl(k_attn_comb, dim3(32), dim3(512), (size_t)SM_F,
            (const float*)attnS, (const float*)hf32, src,
            YH, YL,
            (const bf16*)WcombH, (const bf16*)WcombL,
            XH, XL, AVH, AVL, t*32);
    }

    // ---- final vocab projection: scores = AV @ Wout^T : [1536, 32000] ----
    launch_pdl(gemm3<128,128,32,64,32,2>, dim3(12,250), dim3(256), (size_t)SM_L,
        (const bf16*)AVH, (const bf16*)AVL, 1024,
        (const bf16*)WoutH, (const bf16*)WoutL, 1024,
        out, 32000, 1536, 32000, 1024, 0,
        (const float*)nullptr, (const float*)nullptr,
        (const float*)nullptr, (float*)nullptr,
        (bf16*)nullptr, (bf16*)nullptr, 0,
        (bf16*)nullptr, (bf16*)nullptr, 0, (float*)nullptr);
}

// round 16
// speedup vs baseline: 1.3651x; 1.3651x over previous
#include <cuda_runtime.h>
#include <cuda_bf16.h>
#include <cstdint>
#include <cstddef>

using bf16 = __nv_bfloat16;

#define DI __device__ __forceinline__

// ---------------- constants ----------------
static constexpr int Bb = 32;
static constexpr int Tt = 48;

// ---------------- scratch layout ----------------
constexpr size_t O_ENC_H   = 0;
constexpr size_t O_ENC_L   = O_ENC_H   + (size_t)2048*1024*2;
constexpr size_t O_ATTNS   = O_ENC_L   + (size_t)2048*1024*2;
constexpr size_t O_WPROJ_H = O_ATTNS   + (size_t)2048*1024*4;
constexpr size_t O_WPROJ_L = O_WPROJ_H + (size_t)1024*1024*2;
constexpr size_t O_WWORD_H = O_WPROJ_L + (size_t)1024*1024*2;
constexpr size_t O_WWORD_L = O_WWORD_H + (size_t)4096*512*2;
constexpr size_t O_WCAT_H  = O_WWORD_L + (size_t)4096*512*2;
constexpr size_t O_WCAT_L  = O_WCAT_H  + (size_t)4096*2048*2;
constexpr size_t O_W1_H    = O_WCAT_L  + (size_t)4096*2048*2;
constexpr size_t O_W1_L    = O_W1_H    + (size_t)4096*1024*2;
constexpr size_t O_WCOMB_H = O_W1_L    + (size_t)4096*1024*2;
constexpr size_t O_WCOMB_L = O_WCOMB_H + (size_t)1024*2048*2;
constexpr size_t O_WOUT_H  = O_WCOMB_L + (size_t)1024*2048*2;
constexpr size_t O_WOUT_L  = O_WOUT_H  + (size_t)32000*1024*2;
constexpr size_t O_BIAS0   = O_WOUT_L  + (size_t)32000*1024*2;
constexpr size_t O_BIAS1   = O_BIAS0   + (size_t)4096*4;
constexpr size_t O_AEMB_H  = O_BIAS1   + (size_t)4096*4;
constexpr size_t O_AEMB_L  = O_AEMB_H  + (size_t)1536*512*2;
constexpr size_t O_GWORD   = O_AEMB_L  + (size_t)1536*512*2;
constexpr size_t O_X_H     = O_GWORD   + (size_t)1536*4096*4;
constexpr size_t O_X_L     = O_X_H     + (size_t)32*2048*2;
constexpr size_t O_Y_H     = O_X_L     + (size_t)32*2048*2;
constexpr size_t O_Y_L     = O_Y_H     + (size_t)32*2048*2;
constexpr size_t O_HMID_H  = O_Y_L     + (size_t)32*2048*2;
constexpr size_t O_HMID_L  = O_HMID_H  + (size_t)32*1024*2;
constexpr size_t O_HF32    = O_HMID_L  + (size_t)32*1024*2;
constexpr size_t O_CPREV   = O_HF32    + (size_t)32*1024*4;
constexpr size_t O_CMID    = O_CPREV   + (size_t)32*1024*4;
constexpr size_t O_AV_H    = O_CMID    + (size_t)32*1024*4;
constexpr size_t O_AV_L    = O_AV_H    + (size_t)1536*1024*2;
constexpr size_t SCRATCH_BYTES = O_AV_L + (size_t)1536*1024*2;

__device__ __align__(1024) unsigned char g_scratch[SCRATCH_BYTES];

// ---------------- helpers ----------------
DI float sigmoidf_(float x){ return 1.0f/(1.0f+expf(-x)); }

DI void split_store(float v, bf16* ph, bf16* pl){
    bf16 h = __float2bfloat16(v);
    *ph = h;
    *pl = __float2bfloat16(v - __bfloat162float(h));
}

DI void split_q(float4 v, __nv_bfloat162* h2, __nv_bfloat162* l2, size_t i){
    bf16 h0 = __float2bfloat16(v.x), h1 = __float2bfloat16(v.y);
    bf16 h2v = __float2bfloat16(v.z), h3 = __float2bfloat16(v.w);
    bf16 l0 = __float2bfloat16(v.x - __bfloat162float(h0));
    bf16 l1 = __float2bfloat16(v.y - __bfloat162float(h1));
    bf16 l2v = __float2bfloat16(v.z - __bfloat162float(h2v));
    bf16 l3 = __float2bfloat16(v.w - __bfloat162float(h3));
    h2[i*2]   = __nv_bfloat162(h0, h1);
    h2[i*2+1] = __nv_bfloat162(h2v, h3);
    l2[i*2]   = __nv_bfloat162(l0, l1);
    l2[i*2+1] = __nv_bfloat162(l2v, l3);
}

DI void cpasync16(void* sdst, const void* gsrc){
    uint32_t sa = (uint32_t)__cvta_generic_to_shared(sdst);
    asm volatile("cp.async.cg.shared.global [%0], [%1], 16;\n" :: "r"(sa), "l"(gsrc));
}
DI void cpcommit(){ asm volatile("cp.async.commit_group;\n"); }
template<int N> DI void cpwait(){ asm volatile("cp.async.wait_group %0;\n" :: "n"(N)); }

DI void mma_bf16(float* c, const uint32_t* a, const uint32_t* b){
    asm volatile(
        "mma.sync.aligned.m16n8k16.row.col.f32.bf16.bf16.f32 "
        "{%0,%1,%2,%3}, {%4,%5,%6,%7}, {%8,%9}, {%0,%1,%2,%3};\n"
        : "+f"(c[0]), "+f"(c[1]), "+f"(c[2]), "+f"(c[3])
        : "r"(a[0]), "r"(a[1]), "r"(a[2]), "r"(a[3]), "r"(b[0]), "r"(b[1]));
}

// ---------------- prep kernels (vectorized) ----------------
__global__ void k_split_plain4(const float4* __restrict__ src, __nv_bfloat162* __restrict__ h2,
                               __nv_bfloat162* __restrict__ l2, size_t n4){
    for (size_t i = (size_t)blockIdx.x*blockDim.x + threadIdx.x; i < n4;
         i += (size_t)gridDim.x*blockDim.x)
        split_q(src[i], h2, l2, i);
}

// enc [b*64+s][k] <- src_encodings[s][b][k]  (float4 over k)
__global__ void k_split_enc4(const float4* __restrict__ src4, __nv_bfloat162* __restrict__ h2,
                             __nv_bfloat162* __restrict__ l2){
    size_t n4 = (size_t)2048*256;
    for (size_t i = (size_t)blockIdx.x*blockDim.x + threadIdx.x; i < n4;
         i += (size_t)gridDim.x*blockDim.x){
        int r = (int)(i >> 8), kq = (int)(i & 255);
        int b = r >> 6, s = r & 63;
        split_q(src4[(size_t)(s*Bb + b)*256 + kq], h2, l2, i);
    }
}

// permuted row r = 4*ch + gate ; source row = gate*1024 + ch
DI int perm_src_row(int r){ return (r & 3)*1024 + (r >> 2); }

__global__ void k_build_wword4(const float4* __restrict__ W4, __nv_bfloat162* __restrict__ h2,
                               __nv_bfloat162* __restrict__ l2){
    size_t n4 = (size_t)4096*128;
    for (size_t i = (size_t)blockIdx.x*blockDim.x + threadIdx.x; i < n4;
         i += (size_t)gridDim.x*blockDim.x){
        int r = (int)(i >> 7), kq = (int)(i & 127);
        split_q(W4[(size_t)perm_src_row(r)*384 + kq], h2, l2, i);
    }
}

__global__ void k_build_wcat4(const float4* __restrict__ Wih0_4, const float4* __restrict__ Whh0_4,
                              __nv_bfloat162* __restrict__ h2, __nv_bfloat162* __restrict__ l2){
    size_t n4 = (size_t)4096*512;
    for (size_t i = (size_t)blockIdx.x*blockDim.x + threadIdx.x; i < n4;
         i += (size_t)gridDim.x*blockDim.x){
        int r = (int)(i >> 9), kq = (int)(i & 511);
        int sr = perm_src_row(r);
        float4 v = (kq < 256) ? Wih0_4[(size_t)sr*384 + 128 + kq]
                              : Whh0_4[(size_t)sr*256 + (kq - 256)];
        split_q(v, h2, l2, i);
    }
}

__global__ void k_build_w1_4(const float4* __restrict__ Wih1_4, const float4* __restrict__ Whh1_4,
                             __nv_bfloat162* __restrict__ h2, __nv_bfloat162* __restrict__ l2){
    size_t n4 = (size_t)4096*256;
    for (size_t i = (size_t)blockIdx.x*blockDim.x + threadIdx.x; i < n4;
         i += (size_t)gridDim.x*blockDim.x){
        int r = (int)(i >> 8), kq = (int)(i & 255);
        int sr = perm_src_row(r);
        float4 a = Wih1_4[(size_t)sr*256 + kq];
        float4 b = Whh1_4[(size_t)sr*256 + kq];
        float4 v = make_float4(a.x+b.x, a.y+b.y, a.z+b.z, a.w+b.w);
        split_q(v, h2, l2, i);
    }
}

__global__ void k_build_bias(const float* __restrict__ bi0, const float* __restrict__ bh0,
                             const float* __restrict__ bi1, const float* __restrict__ bh1,
                             float* __restrict__ o0, float* __restrict__ o1){
    int r = blockIdx.x*blockDim.x + threadIdx.x;
    if (r < 4096){
        int sr = perm_src_row(r);
        o0[r] = bi0[sr] + bh0[sr];
        o1[r] = bi1[sr] + bh1[sr];
    }
}

__global__ void k_gather_emb4(const float4* __restrict__ emb4, const int* __restrict__ tgt,
                              __nv_bfloat162* __restrict__ h2, __nv_bfloat162* __restrict__ l2){
    size_t n4 = (size_t)1536*128;
    for (size_t i = (size_t)blockIdx.x*blockDim.x + threadIdx.x; i < n4;
         i += (size_t)gridDim.x*blockDim.x){
        int m = (int)(i >> 7), kq = (int)(i & 127);
        split_q(emb4[(size_t)tgt[m]*128 + kq], h2, l2, i);
    }
}

__global__ void k_init_state(const float* __restrict__ h0, const float* __restrict__ c0,
                             float* __restrict__ cprev, bf16* __restrict__ Xh,
                             bf16* __restrict__ Xl){
    int i = blockIdx.x*blockDim.x + threadIdx.x;
    if (i < 32*1024){
        int row = i >> 10, k = i & 1023;
        cprev[i] = c0[i];
        bf16 z = __float2bfloat16(0.0f);
        Xh[row*2048 + k] = z;
        Xl[row*2048 + k] = z;
        split_store(h0[i], Xh + row*2048 + 1024 + k, Xl + row*2048 + 1024 + k);
    }
}

// ---------------- attention kernel (512 threads, trigger at end) ----------------
__global__ void __launch_bounds__(512)
k_attention(const float* __restrict__ attnS,   // [2048,1024], row=b*64+s
            const float* __restrict__ hf,      // [32,1024]
            const float* __restrict__ src,     // [64,32,1024]
            bf16* __restrict__ Yh, bf16* __restrict__ Yl){ // [32,2048]
    cudaGridDependencySynchronize();

    int b = blockIdx.x;
    int tid = threadIdx.x, w = tid >> 5, lane = tid & 31;
    __shared__ float sh[1024];
    __shared__ float salpha[64];
    __shared__ float sinv;

    for (int i = tid; i < 1024; i += 512) sh[i] = hf[b*1024 + i];
    __syncthreads();

    #pragma unroll
    for (int j = 0; j < 4; j++){
        int s = w + 16*j;
        const float* row = attnS + (size_t)(b*64 + s)*1024;
        float acc = 0.f;
        #pragma unroll 8
        for (int k = lane; k < 1024; k += 32) acc += row[k]*sh[k];
        #pragma unroll
        for (int o = 16; o > 0; o >>= 1) acc += __shfl_xor_sync(0xffffffffu, acc, o);
        if (lane == 0) salpha[s] = acc;
    }
    __syncthreads();
    if (w == 0){
        float a0 = salpha[lane], a1 = salpha[lane + 32];
        float m = fmaxf(a0, a1);
        #pragma unroll
        for (int o = 16; o > 0; o >>= 1) m = fmaxf(m, __shfl_xor_sync(0xffffffffu, m, o));
        float e0 = expf(a0 - m), e1 = expf(a1 - m);
        salpha[lane] = e0; salpha[lane + 32] = e1;
        float su = e0 + e1;
        #pragma unroll
        for (int o = 16; o > 0; o >>= 1) su += __shfl_xor_sync(0xffffffffu, su, o);
        if (lane == 0) sinv = 1.0f/su;
    }
    __syncthreads();
    float inv = sinv;
    for (int e = tid; e < 1024; e += 512){
        float acc = 0.f;
        #pragma unroll 16
        for (int s = 0; s < 64; s++)
            acc += salpha[s]*src[((size_t)(s*Bb + b))*1024 + e];
        acc *= inv;
        split_store(acc, Yh + b*2048 + 1024 + e, Yl + b*2048 + 1024 + e);
    }
    cudaTriggerProgrammaticLaunchCompletion();
}

// ---------------- 3-pass split-bf16 GEMM (PDL, trigger at end) ----------------
// C[M,N] = A[M,K] * B[N,K]^T  with A ~ Ah+Al, B ~ Bh+Bl (3 mma passes).
// epi: 0=store, 1=store+bias, 2=LSTM cell (interleaved gates), 3=tanh+split
template<int BM, int BN, int BK, int WM, int WN, int STAGES>
__global__ void __launch_bounds__(32*(BM/WM)*(BN/WN))
gemm3(const bf16* __restrict__ Ah, const bf16* __restrict__ Al, int lda,
      const bf16* __restrict__ Bh, const bf16* __restrict__ Bl, int ldb,
      float* __restrict__ C, int ldc,
      int M, int N, int K, int epi,
      const float* __restrict__ addend,
      const float* __restrict__ bias,
      const float* __restrict__ cin, float* __restrict__ cout,
      bf16* __restrict__ h1h, bf16* __restrict__ h1l, int h1ld,
      bf16* __restrict__ h2h, bf16* __restrict__ h2l, int h2ld,
      float* __restrict__ hf32,
      bf16* __restrict__ o2h, bf16* __restrict__ o2l, int o2ld, int o2r0)
{
    constexpr int WARPS_M = BM/WM, WARPS_N = BN/WN;
    constexpr int THREADS = 32*WARPS_M*WARPS_N;
    constexpr int MF = WM/16, NF = WN/8;
    constexpr int BKP = BK + 8;
    constexpr int WRD = BKP/2;
    constexpr int CH  = BK/8;
    constexpr int ASZ = BM*BKP, BSZ = BN*BKP;
    constexpr int STG = 2*ASZ + 2*BSZ;
    extern __shared__ bf16 smem[];

    const int tid = threadIdx.x, wid = tid >> 5, lane = tid & 31;
    const int wm = wid / WARPS_N, wn = wid % WARPS_N;
    const int g = lane >> 2, t = lane & 3;
    const int bm0 = blockIdx.x*BM, bn0 = blockIdx.y*BN;

    float acc[MF][NF][4];
    #pragma unroll
    for (int a = 0; a < MF; a++)
        #pragma unroll
        for (int b = 0; b < NF; b++)
            #pragma unroll
            for (int c = 0; c < 4; c++) acc[a][b][c] = 0.f;

    const int KT = K/BK;

    auto loadB = [&](int kt, int st){
        bf16* s = smem + st*STG;
        int k0 = kt*BK;
        for (int c = tid; c < BN*CH; c += THREADS){
            int r = c/CH, cc = c%CH;
            size_t go = (size_t)(bn0 + r)*ldb + k0 + cc*8;
            cpasync16(s + 2*ASZ + r*BKP + cc*8, Bh + go);
            cpasync16(s + 2*ASZ + BSZ + r*BKP + cc*8, Bl + go);
        }
    };
    auto loadA = [&](int kt, int st){
        bf16* s = smem + st*STG;
        int k0 = kt*BK;
        for (int c = tid; c < BM*CH; c += THREADS){
            int r = c/CH, cc = c%CH;
            size_t go = (size_t)(bm0 + r)*lda + k0 + cc*8;
            cpasync16(s + r*BKP + cc*8, Ah + go);
            cpasync16(s + ASZ + r*BKP + cc*8, Al + go);
        }
    };

    // Weight (B) prefetch overlaps the predecessor tail; sync before touching A.
    #pragma unroll
    for (int s = 0; s < STAGES-1; s++) loadB(s, s);
    cudaGridDependencySynchronize();
    loadA(0, 0); cpcommit();
    #pragma unroll
    for (int s = 1; s < STAGES-1; s++){ loadA(s, s); cpcommit(); }

    for (int kt = 0; kt < KT; kt++){
        cpwait<STAGES-2>();
        __syncthreads();
        int nstage = kt + STAGES - 1;
        if (nstage < KT){ loadB(nstage, nstage % STAGES); loadA(nstage, nstage % STAGES); }
        cpcommit();

        const bf16* s = smem + (kt % STAGES)*STG;
        const uint32_t* sAh = (const uint32_t*)s;
        const uint32_t* sAl = (const uint32_t*)(s + ASZ);
        const uint32_t* sBh = (const uint32_t*)(s + 2*ASZ);
        const uint32_t* sBl = (const uint32_t*)(s + 2*ASZ + BSZ);
        #pragma unroll
        for (int ks = 0; ks < BK/16; ks++){
            uint32_t af[MF][4], alf[MF][4], bhf[NF][2], blf[NF][2];
            #pragma unroll
            for (int mf = 0; mf < MF; mf++){
                int r0 = wm*WM + mf*16;
                int i0 = (r0 + g)*WRD + ks*8 + t;
                int i1 = (r0 + g + 8)*WRD + ks*8 + t;
                af[mf][0] = sAh[i0];   af[mf][1] = sAh[i1];
                af[mf][2] = sAh[i0+4]; af[mf][3] = sAh[i1+4];
                alf[mf][0] = sAl[i0];   alf[mf][1] = sAl[i1];
                alf[mf][2] = sAl[i0+4]; alf[mf][3] = sAl[i1+4];
            }
            #pragma unroll
            for (int nf = 0; nf < NF; nf++){
                int cb = wn*WN + nf*8 + g;
                int i0 = cb*WRD + ks*8 + t;
                bhf[nf][0] = sBh[i0]; bhf[nf][1] = sBh[i0+4];
                blf[nf][0] = sBl[i0]; blf[nf][1] = sBl[i0+4];
            }
            #pragma unroll
            for (int mf = 0; mf < MF; mf++)
                #pragma unroll
                for (int nf = 0; nf < NF; nf++){
                    mma_bf16(acc[mf][nf], af[mf],  bhf[nf]);
                    mma_bf16(acc[mf][nf], alf[mf], bhf[nf]);
                    mma_bf16(acc[mf][nf], af[mf],  blf[nf]);
                }
        }
        __syncthreads();
    }

    // epilogue
    #pragma unroll
    for (int mf = 0; mf < MF; mf++){
        #pragma unroll
        for (int nf = 0; nf < NF; nf++){
            #pragma unroll
            for (int half = 0; half < 2; half++){
                int row = bm0 + wm*WM + mf*16 + g + half*8;
                int col = bn0 + wn*WN + nf*8 + 2*t;
                float v0 = acc[mf][nf][half*2 + 0];
                float v1 = acc[mf][nf][half*2 + 1];
                if (epi <= 1){
                    if (epi == 1){ v0 += bias[col]; v1 += bias[col+1]; }
                    C[(size_t)row*ldc + col]     = v0;
                    C[(size_t)row*ldc + col + 1] = v1;
                } else if (epi == 2){
                    if (addend){ v0 += addend[(size_t)row*N + col];
                                 v1 += addend[(size_t)row*N + col + 1]; }
                    if (bias){ v0 += bias[col]; v1 += bias[col+1]; }
                    float w0 = __shfl_xor_sync(0xffffffffu, v0, 1);
                    float w1 = __shfl_xor_sync(0xffffffffu, v1, 1);
                    if ((t & 1) == 0){
                        // even lanes hold (i,f); partner holds (g,o)
                        float ig = sigmoidf_(v0), fg = sigmoidf_(v1);
                        float gg = tanhf(w0),    og = sigmoidf_(w1);
                        int ch = col >> 2;
                        float cn = fg*cin[row*1024 + ch] + ig*gg;
                        float hn = og*tanhf(cn);
                        cout[row*1024 + ch] = cn;
                        bf16 hh = __float2bfloat16(hn);
                        bf16 hl = __float2bfloat16(hn - __bfloat162float(hh));
                        h1h[row*h1ld + ch] = hh;
                        h1l[row*h1ld + ch] = hl;
                        if (h2h){ h2h[row*h2ld + ch] = hh; h2l[row*h2ld + ch] = hl; }
                        if (hf32) hf32[row*1024 + ch] = hn;
                    }
                } else { // epi == 3 : tanh + split to two destinations
                    float a0 = tanhf(v0), a1 = tanhf(v1);
                    bf16 p0 = __float2bfloat16(a0);
                    bf16 q0 = __float2bfloat16(a0 - __bfloat162float(p0));
                    bf16 p1 = __float2bfloat16(a1);
                    bf16 q1 = __float2bfloat16(a1 - __bfloat162float(p1));
                    h1h[row*h1ld + col]   = p0; h1l[row*h1ld + col]   = q0;
                    h1h[row*h1ld + col+1] = p1; h1l[row*h1ld + col+1] = q1;
                    o2h[(size_t)(o2r0+row)*o2ld + col]   = p0;
                    o2l[(size_t)(o2r0+row)*o2ld + col]   = q0;
                    o2h[(size_t)(o2r0+row)*o2ld + col+1] = p1;
                    o2l[(size_t)(o2r0+row)*o2ld + col+1] = q1;
                }
            }
        }
    }
    cudaTriggerProgrammaticLaunchCompletion();
}

// ---------------- host launch ----------------
static constexpr int SM_L = 2*(2*128+2*128)*(32+8)*2;    // 81920 (2 blocks/SM)
static constexpr int SM_G = 3*(2*32+2*32)*(256+8)*2;     // 202752 (BK=256 gates)
static constexpr int SM_C = 3*(2*32+2*16)*(256+8)*2;     // 152064 (BK=256 combine)

template<typename F, typename... Args>
static void launch_pdl(F f, dim3 g, dim3 b, size_t sm, Args... args){
    cudaLaunchConfig_t cfg = {};
    cfg.gridDim = g; cfg.blockDim = b; cfg.dynamicSmemBytes = sm; cfg.stream = 0;
    cudaLaunchAttribute at[1];
    at[0].id = cudaLaunchAttributeProgrammaticStreamSerialization;
    at[0].val.programmaticStreamSerializationAllowed = 1;
    cfg.attrs = at; cfg.numAttrs = 1;
    cudaLaunchKernelEx(&cfg, f, args...);
}

extern "C" void kernel_launch(void* const* d_in, const int* in_sizes, int n_in,
                              void* d_out, int out_size){
    const float* src   = (const float*)d_in[0];
    const float* h0    = (const float*)d_in[1];
    const float* c0    = (const float*)d_in[2];
    const float* emb   = (const float*)d_in[3];
    const float* Wproj = (const float*)d_in[4];
    const float* Wcomb = (const float*)d_in[5];
    const float* Wout  = (const float*)d_in[6];
    const float* Wih0  = (const float*)d_in[7];
    const float* Whh0  = (const float*)d_in[8];
    const float* bih0  = (const float*)d_in[9];
    const float* bhh0  = (const float*)d_in[10];
    const float* Wih1  = (const float*)d_in[11];
    const float* Whh1  = (const float*)d_in[12];
    const float* bih1  = (const float*)d_in[13];
    const float* bhh1  = (const float*)d_in[14];
    const int*   tgt   = (const int*)d_in[15];
    float* out = (float*)d_out;

    void* basep = nullptr;
    cudaGetSymbolAddress(&basep, g_scratch);
    unsigned char* base = (unsigned char*)basep;

    bf16*  encH   = (bf16*)(base + O_ENC_H);
    bf16*  encL   = (bf16*)(base + O_ENC_L);
    float* attnS  = (float*)(base + O_ATTNS);
    bf16*  WprojH = (bf16*)(base + O_WPROJ_H);
    bf16*  WprojL = (bf16*)(base + O_WPROJ_L);
    bf16*  WwordH = (bf16*)(base + O_WWORD_H);
    bf16*  WwordL = (bf16*)(base + O_WWORD_L);
    bf16*  WcatH  = (bf16*)(base + O_WCAT_H);
    bf16*  WcatL  = (bf16*)(base + O_WCAT_L);
    bf16*  W1H    = (bf16*)(base + O_W1_H);
    bf16*  W1L    = (bf16*)(base + O_W1_L);
    bf16*  WcombH = (bf16*)(base + O_WCOMB_H);
    bf16*  WcombL = (bf16*)(base + O_WCOMB_L);
    bf16*  WoutH  = (bf16*)(base + O_WOUT_H);
    bf16*  WoutL  = (bf16*)(base + O_WOUT_L);
    float* bias0  = (float*)(base + O_BIAS0);
    float* bias1  = (float*)(base + O_BIAS1);
    bf16*  AembH  = (bf16*)(base + O_AEMB_H);
    bf16*  AembL  = (bf16*)(base + O_AEMB_L);
    float* Gword  = (float*)(base + O_GWORD);
    bf16*  XH     = (bf16*)(base + O_X_H);
    bf16*  XL     = (bf16*)(base + O_X_L);
    bf16*  YH     = (bf16*)(base + O_Y_H);
    bf16*  YL     = (bf16*)(base + O_Y_L);
    bf16*  HmidH  = (bf16*)(base + O_HMID_H);
    bf16*  HmidL  = (bf16*)(base + O_HMID_L);
    float* hf32   = (float*)(base + O_HF32);
    float* cprev  = (float*)(base + O_CPREV);
    float* cmid   = (float*)(base + O_CMID);
    bf16*  AVH    = (bf16*)(base + O_AV_H);
    bf16*  AVL    = (bf16*)(base + O_AV_L);

    cudaFuncSetAttribute((const void*)gemm3<128,128,32,64,32,2>,
                         cudaFuncAttributeMaxDynamicSharedMemorySize, SM_L);
    cudaFuncSetAttribute((const void*)gemm3<32,32,256,16,8,3>,
                         cudaFuncAttributeMaxDynamicSharedMemorySize, SM_G);
    cudaFuncSetAttribute((const void*)gemm3<32,16,256,16,8,3>,
                         cudaFuncAttributeMaxDynamicSharedMemorySize, SM_C);

    // ---- setup (vectorized splits/builders) ----
    k_split_enc4<<<2048,256>>>((const float4*)src, (__nv_bfloat162*)encH,
                               (__nv_bfloat162*)encL);
    k_split_plain4<<<2048,256>>>((const float4*)Wproj, (__nv_bfloat162*)WprojH,
                                 (__nv_bfloat162*)WprojL, (size_t)1024*1024/4);
    k_split_plain4<<<4096,256>>>((const float4*)Wcomb, (__nv_bfloat162*)WcombH,
                                 (__nv_bfloat162*)WcombL, (size_t)1024*2048/4);
    k_split_plain4<<<8192,256>>>((const float4*)Wout, (__nv_bfloat162*)WoutH,
                                 (__nv_bfloat162*)WoutL, (size_t)32000*1024/4);
    k_build_wword4<<<2048,256>>>((const float4*)Wih0, (__nv_bfloat162*)WwordH,
                                 (__nv_bfloat162*)WwordL);
    k_build_wcat4<<<4096,256>>>((const float4*)Wih0, (const float4*)Whh0,
                                (__nv_bfloat162*)WcatH, (__nv_bfloat162*)WcatL);
    k_build_w1_4<<<2048,256>>>((const float4*)Wih1, (const float4*)Whh1,
                               (__nv_bfloat162*)W1H, (__nv_bfloat162*)W1L);
    k_build_bias<<<16,256>>>(bih0, bhh0, bih1, bhh1, bias0, bias1);
    k_gather_emb4<<<1024,256>>>((const float4*)emb, tgt,
                                (__nv_bfloat162*)AembH, (__nv_bfloat162*)AembL);
    k_init_state<<<128,256>>>(h0, c0, cprev, XH, XL);

    // attn_scores = enc @ Wproj^T : [2048,1024]
    launch_pdl(gemm3<128,128,32,64,32,2>, dim3(16,8), dim3(256), (size_t)SM_L,
        (const bf16*)encH, (const bf16*)encL, 1024,
        (const bf16*)WprojH, (const bf16*)WprojL, 1024,
        attnS, 1024, 2048, 1024, 1024, 0,
        (const float*)nullptr, (const float*)nullptr,
        (const float*)nullptr, (float*)nullptr,
        (bf16*)nullptr, (bf16*)nullptr, 0,
        (bf16*)nullptr, (bf16*)nullptr, 0, (float*)nullptr,
        (bf16*)nullptr, (bf16*)nullptr, 0, 0);

    // G_word = emb_gathered @ Wword^T + bias0 : [1536,4096] (permuted gates)
    launch_pdl(gemm3<128,128,32,64,32,2>, dim3(12,32), dim3(256), (size_t)SM_L,
        (const bf16*)AembH, (const bf16*)AembL, 512,
        (const bf16*)WwordH, (const bf16*)WwordL, 512,
        Gword, 4096, 1536, 4096, 512, 1,
        (const float*)nullptr, (const float*)bias0,
        (const float*)nullptr, (float*)nullptr,
        (bf16*)nullptr, (bf16*)nullptr, 0,
        (bf16*)nullptr, (bf16*)nullptr, 0, (float*)nullptr,
        (bf16*)nullptr, (bf16*)nullptr, 0, 0);

    // ---- sequential decode loop: 4 kernels per step (BK=256 loop GEMMs) ----
    for (int t = 0; t < Tt; t++){
        launch_pdl(gemm3<32,32,256,16,8,3>, dim3(1,128), dim3(256), (size_t)SM_G,
            (const bf16*)XH, (const bf16*)XL, 2048,
            (const bf16*)WcatH, (const bf16*)WcatL, 2048,
            (float*)nullptr, 0, 32, 4096, 2048, 2,
            (const float*)(Gword + (size_t)t*32*4096), (const float*)nullptr,
            (const float*)cprev, cmid,
            HmidH, HmidL, 1024,
            (bf16*)nullptr, (bf16*)nullptr, 0, (float*)nullptr,
            (bf16*)nullptr, (bf16*)nullptr, 0, 0);

        launch_pdl(gemm3<32,32,256,16,8,3>, dim3(1,128), dim3(256), (size_t)SM_G,
            (const bf16*)HmidH, (const bf16*)HmidL, 1024,
            (const bf16*)W1H, (const bf16*)W1L, 1024,
            (float*)nullptr, 0, 32, 4096, 1024, 2,
            (const float*)nullptr, (const float*)bias1,
            (const float*)cmid, cprev,
            YH, YL, 2048,
            XH + 1024, XL + 1024, 2048, hf32,
            (bf16*)nullptr, (bf16*)nullptr, 0, 0);

        {
            cudaLaunchConfig_t cfg = {};
            cfg.gridDim = dim3(32); cfg.blockDim = dim3(512);
            cfg.dynamicSmemBytes = 0; cfg.stream = 0;
            cudaLaunchAttribute at[1];
            at[0].id = cudaLaunchAttributeProgrammaticStreamSerialization;
            at[0].val.programmaticStreamSerializationAllowed = 1;
            cfg.attrs = at; cfg.numAttrs = 1;
            cudaLaunchKernelEx(&cfg, k_attention,
                (const float*)attnS, (const float*)hf32, src, YH, YL);
        }

        // combine: av = tanh([h|ctx] @ Wcomb^T) -> X[:,0:1024] and AV[t]
        launch_pdl(gemm3<32,16,256,16,8,3>, dim3(1,64), dim3(128), (size_t)SM_C,
            (const bf16*)YH, (const bf16*)YL, 2048,
            (const bf16*)WcombH, (const bf16*)WcombL, 2048,
            (float*)nullptr, 0, 32, 1024, 2048, 3,
            (const float*)nullptr, (const float*)nullptr,
            (const float*)nullptr, (float*)nullptr,
            XH, XL, 2048,
            (bf16*)nullptr, (bf16*)nullptr, 0, (float*)nullptr,
            AVH, AVL, 1024, t*32);
    }

    // ---- final vocab projection: scores = AV @ Wout^T : [1536, 32000] ----
    launch_pdl(gemm3<128,128,32,64,32,2>, dim3(12,250), dim3(256), (size_t)SM_L,
        (const bf16*)AVH, (const bf16*)AVL, 1024,
        (const bf16*)WoutH, (const bf16*)WoutL, 1024,
        out, 32000, 1536, 32000, 1024, 0,
        (const float*)nullptr, (const float*)nullptr,
        (const float*)nullptr, (float*)nullptr,
        (bf16*)nullptr, (bf16*)nullptr, 0,
        (bf16*)nullptr, (bf16*)nullptr, 0, (float*)nullptr,
        (bf16*)nullptr, (bf16*)nullptr, 0, 0);
}

// round 17
// speedup vs baseline: 1.4241x; 1.0432x over previous
#include <cuda_runtime.h>
#include <cuda_bf16.h>
#include <cuda_fp16.h>
#include <cstdint>
#include <cstddef>

using bf16 = __nv_bfloat16;

#define DI __device__ __forceinline__

// ---------------- constants ----------------
static constexpr int Bb = 32;
static constexpr int Tt = 48;

// ---------------- scratch layout ----------------
constexpr size_t O_ENC_H   = 0;
constexpr size_t O_ENC_L   = O_ENC_H   + (size_t)2048*1024*2;
constexpr size_t O_ATTNS   = O_ENC_L   + (size_t)2048*1024*2;
constexpr size_t O_WPROJ_H = O_ATTNS   + (size_t)2048*1024*4;
constexpr size_t O_WPROJ_L = O_WPROJ_H + (size_t)1024*1024*2;
constexpr size_t O_WWORD_H = O_WPROJ_L + (size_t)1024*1024*2;
constexpr size_t O_WWORD_L = O_WWORD_H + (size_t)4096*512*2;
constexpr size_t O_WCAT_H  = O_WWORD_L + (size_t)4096*512*2;
constexpr size_t O_WCAT_L  = O_WCAT_H  + (size_t)4096*2048*2;
constexpr size_t O_W1_H    = O_WCAT_L  + (size_t)4096*2048*2;
constexpr size_t O_W1_L    = O_W1_H    + (size_t)4096*1024*2;
constexpr size_t O_WCOMB_H = O_W1_L    + (size_t)4096*1024*2;
constexpr size_t O_WCOMB_L = O_WCOMB_H + (size_t)1024*2048*2;
constexpr size_t O_WOUT_H  = O_WCOMB_L + (size_t)1024*2048*2;   // fp16
constexpr size_t O_WOUT_L  = O_WOUT_H  + (size_t)32000*1024*2;  // fp16
constexpr size_t O_BIAS0   = O_WOUT_L  + (size_t)32000*1024*2;
constexpr size_t O_BIAS1   = O_BIAS0   + (size_t)4096*4;
constexpr size_t O_AEMB_H  = O_BIAS1   + (size_t)4096*4;
constexpr size_t O_AEMB_L  = O_AEMB_H  + (size_t)1536*512*2;
constexpr size_t O_GWORD   = O_AEMB_L  + (size_t)1536*512*2;
constexpr size_t O_X_H     = O_GWORD   + (size_t)1536*4096*4;
constexpr size_t O_X_L     = O_X_H     + (size_t)32*2048*2;
constexpr size_t O_Y_H     = O_X_L     + (size_t)32*2048*2;
constexpr size_t O_Y_L     = O_Y_H     + (size_t)32*2048*2;
constexpr size_t O_HMID_H  = O_Y_L     + (size_t)32*2048*2;
constexpr size_t O_HMID_L  = O_HMID_H  + (size_t)32*1024*2;
constexpr size_t O_HF32    = O_HMID_L  + (size_t)32*1024*2;
constexpr size_t O_CPREV   = O_HF32    + (size_t)32*1024*4;
constexpr size_t O_CMID    = O_CPREV   + (size_t)32*1024*4;
constexpr size_t O_AV_H    = O_CMID    + (size_t)32*1024*4;     // fp16
constexpr size_t O_AV_L    = O_AV_H    + (size_t)1536*1024*2;   // fp16
constexpr size_t SCRATCH_BYTES = O_AV_L + (size_t)1536*1024*2;

__device__ __align__(1024) unsigned char g_scratch[SCRATCH_BYTES];

// ---------------- helpers ----------------
DI float sigmoidf_(float x){ return 1.0f/(1.0f+expf(-x)); }

DI void split_store(float v, bf16* ph, bf16* pl){
    bf16 h = __float2bfloat16(v);
    *ph = h;
    *pl = __float2bfloat16(v - __bfloat162float(h));
}

DI void split_q(float4 v, __nv_bfloat162* h2, __nv_bfloat162* l2, size_t i){
    bf16 h0 = __float2bfloat16(v.x), h1 = __float2bfloat16(v.y);
    bf16 h2v = __float2bfloat16(v.z), h3 = __float2bfloat16(v.w);
    bf16 l0 = __float2bfloat16(v.x - __bfloat162float(h0));
    bf16 l1 = __float2bfloat16(v.y - __bfloat162float(h1));
    bf16 l2v = __float2bfloat16(v.z - __bfloat162float(h2v));
    bf16 l3 = __float2bfloat16(v.w - __bfloat162float(h3));
    h2[i*2]   = __nv_bfloat162(h0, h1);
    h2[i*2+1] = __nv_bfloat162(h2v, h3);
    l2[i*2]   = __nv_bfloat162(l0, l1);
    l2[i*2+1] = __nv_bfloat162(l2v, l3);
}

DI void split_qh(float4 v, __half2* h2, __half2* l2, size_t i){
    __half h0 = __float2half(v.x), h1 = __float2half(v.y);
    __half h2v = __float2half(v.z), h3 = __float2half(v.w);
    __half l0 = __float2half(v.x - __half2float(h0));
    __half l1 = __float2half(v.y - __half2float(h1));
    __half l2v = __float2half(v.z - __half2float(h2v));
    __half l3 = __float2half(v.w - __half2float(h3));
    h2[i*2]   = __half2(h0, h1);
    h2[i*2+1] = __half2(h2v, h3);
    l2[i*2]   = __half2(l0, l1);
    l2[i*2+1] = __half2(l2v, l3);
}

DI void cpasync16(void* sdst, const void* gsrc){
    uint32_t sa = (uint32_t)__cvta_generic_to_shared(sdst);
    asm volatile("cp.async.cg.shared.global [%0], [%1], 16;\n" :: "r"(sa), "l"(gsrc));
}
DI void cpcommit(){ asm volatile("cp.async.commit_group;\n"); }
template<int N> DI void cpwait(){ asm volatile("cp.async.wait_group %0;\n" :: "n"(N)); }

DI void mma_bf16(float* c, const uint32_t* a, const uint32_t* b){
    asm volatile(
        "mma.sync.aligned.m16n8k16.row.col.f32.bf16.bf16.f32 "
        "{%0,%1,%2,%3}, {%4,%5,%6,%7}, {%8,%9}, {%0,%1,%2,%3};\n"
        : "+f"(c[0]), "+f"(c[1]), "+f"(c[2]), "+f"(c[3])
        : "r"(a[0]), "r"(a[1]), "r"(a[2]), "r"(a[3]), "r"(b[0]), "r"(b[1]));
}

DI void mma_f16(float* c, const uint32_t* a, const uint32_t* b){
    asm volatile(
        "mma.sync.aligned.m16n8k16.row.col.f32.f16.f16.f32 "
        "{%0,%1,%2,%3}, {%4,%5,%6,%7}, {%8,%9}, {%0,%1,%2,%3};\n"
        : "+f"(c[0]), "+f"(c[1]), "+f"(c[2]), "+f"(c[3])
        : "r"(a[0]), "r"(a[1]), "r"(a[2]), "r"(a[3]), "r"(b[0]), "r"(b[1]));
}

// ---------------- prep kernels (vectorized) ----------------
__global__ void k_split_plain4(const float4* __restrict__ src, __nv_bfloat162* __restrict__ h2,
                               __nv_bfloat162* __restrict__ l2, size_t n4){
    for (size_t i = (size_t)blockIdx.x*blockDim.x + threadIdx.x; i < n4;
         i += (size_t)gridDim.x*blockDim.x)
        split_q(src[i], h2, l2, i);
}

// fp16 split (for Wout)
__global__ void k_split_plain4h(const float4* __restrict__ src, __half2* __restrict__ h2,
                                __half2* __restrict__ l2, size_t n4){
    for (size_t i = (size_t)blockIdx.x*blockDim.x + threadIdx.x; i < n4;
         i += (size_t)gridDim.x*blockDim.x)
        split_qh(src[i], h2, l2, i);
}

// enc [b*64+s][k] <- src_encodings[s][b][k]  (float4 over k)
__global__ void k_split_enc4(const float4* __restrict__ src4, __nv_bfloat162* __restrict__ h2,
                             __nv_bfloat162* __restrict__ l2){
    size_t n4 = (size_t)2048*256;
    for (size_t i = (size_t)blockIdx.x*blockDim.x + threadIdx.x; i < n4;
         i += (size_t)gridDim.x*blockDim.x){
        int r = (int)(i >> 8), kq = (int)(i & 255);
        int b = r >> 6, s = r & 63;
        split_q(src4[(size_t)(s*Bb + b)*256 + kq], h2, l2, i);
    }
}

// permuted row r = 4*ch + gate ; source row = gate*1024 + ch
DI int perm_src_row(int r){ return (r & 3)*1024 + (r >> 2); }

__global__ void k_build_wword4(const float4* __restrict__ W4, __nv_bfloat162* __restrict__ h2,
                               __nv_bfloat162* __restrict__ l2){
    size_t n4 = (size_t)4096*128;
    for (size_t i = (size_t)blockIdx.x*blockDim.x + threadIdx.x; i < n4;
         i += (size_t)gridDim.x*blockDim.x){
        int r = (int)(i >> 7), kq = (int)(i & 127);
        split_q(W4[(size_t)perm_src_row(r)*384 + kq], h2, l2, i);
    }
}

__global__ void k_build_wcat4(const float4* __restrict__ Wih0_4, const float4* __restrict__ Whh0_4,
                              __nv_bfloat162* __restrict__ h2, __nv_bfloat162* __restrict__ l2){
    size_t n4 = (size_t)4096*512;
    for (size_t i = (size_t)blockIdx.x*blockDim.x + threadIdx.x; i < n4;
         i += (size_t)gridDim.x*blockDim.x){
        int r = (int)(i >> 9), kq = (int)(i & 511);
        int sr = perm_src_row(r);
        float4 v = (kq < 256) ? Wih0_4[(size_t)sr*384 + 128 + kq]
                              : Whh0_4[(size_t)sr*256 + (kq - 256)];
        split_q(v, h2, l2, i);
    }
}

__global__ void k_build_w1_4(const float4* __restrict__ Wih1_4, const float4* __restrict__ Whh1_4,
                             __nv_bfloat162* __restrict__ h2, __nv_bfloat162* __restrict__ l2){
    size_t n4 = (size_t)4096*256;
    for (size_t i = (size_t)blockIdx.x*blockDim.x + threadIdx.x; i < n4;
         i += (size_t)gridDim.x*blockDim.x){
        int r = (int)(i >> 8), kq = (int)(i & 255);
        int sr = perm_src_row(r);
        float4 a = Wih1_4[(size_t)sr*256 + kq];
        float4 b = Whh1_4[(size_t)sr*256 + kq];
        float4 v = make_float4(a.x+b.x, a.y+b.y, a.z+b.z, a.w+b.w);
        split_q(v, h2, l2, i);
    }
}

__global__ void k_build_bias(const float* __restrict__ bi0, const float* __restrict__ bh0,
                             const float* __restrict__ bi1, const float* __restrict__ bh1,
                             float* __restrict__ o0, float* __restrict__ o1){
    int r = blockIdx.x*blockDim.x + threadIdx.x;
    if (r < 4096){
        int sr = perm_src_row(r);
        o0[r] = bi0[sr] + bh0[sr];
        o1[r] = bi1[sr] + bh1[sr];
    }
}

__global__ void k_gather_emb4(const float4* __restrict__ emb4, const int* __restrict__ tgt,
                              __nv_bfloat162* __restrict__ h2, __nv_bfloat162* __restrict__ l2){
    size_t n4 = (size_t)1536*128;
    for (size_t i = (size_t)blockIdx.x*blockDim.x + threadIdx.x; i < n4;
         i += (size_t)gridDim.x*blockDim.x){
        int m = (int)(i >> 7), kq = (int)(i & 127);
        split_q(emb4[(size_t)tgt[m]*128 + kq], h2, l2, i);
    }
}

__global__ void k_init_state(const float* __restrict__ h0, const float* __restrict__ c0,
                             float* __restrict__ cprev, bf16* __restrict__ Xh,
                             bf16* __restrict__ Xl){
    int i = blockIdx.x*blockDim.x + threadIdx.x;
    if (i < 32*1024){
        int row = i >> 10, k = i & 1023;
        cprev[i] = c0[i];
        bf16 z = __float2bfloat16(0.0f);
        Xh[row*2048 + k] = z;
        Xl[row*2048 + k] = z;
        split_store(h0[i], Xh + row*2048 + 1024 + k, Xl + row*2048 + 1024 + k);
    }
}

// ---------------- attention kernel (512 threads, trigger at end) ----------------
__global__ void __launch_bounds__(512)
k_attention(const float* __restrict__ attnS,   // [2048,1024], row=b*64+s
            const float* __restrict__ hf,      // [32,1024]
            const float* __restrict__ src,     // [64,32,1024]
            bf16* __restrict__ Yh, bf16* __restrict__ Yl){ // [32,2048]
    cudaGridDependencySynchronize();

    int b = blockIdx.x;
    int tid = threadIdx.x, w = tid >> 5, lane = tid & 31;
    __shared__ float sh[1024];
    __shared__ float salpha[64];
    __shared__ float sinv;

    for (int i = tid; i < 1024; i += 512) sh[i] = hf[b*1024 + i];
    __syncthreads();

    #pragma unroll
    for (int j = 0; j < 4; j++){
        int s = w + 16*j;
        const float* row = attnS + (size_t)(b*64 + s)*1024;
        float acc = 0.f;
        #pragma unroll 8
        for (int k = lane; k < 1024; k += 32) acc += row[k]*sh[k];
        #pragma unroll
        for (int o = 16; o > 0; o >>= 1) acc += __shfl_xor_sync(0xffffffffu, acc, o);
        if (lane == 0) salpha[s] = acc;
    }
    __syncthreads();
    if (w == 0){
        float a0 = salpha[lane], a1 = salpha[lane + 32];
        float m = fmaxf(a0, a1);
        #pragma unroll
        for (int o = 16; o > 0; o >>= 1) m = fmaxf(m, __shfl_xor_sync(0xffffffffu, m, o));
        float e0 = expf(a0 - m), e1 = expf(a1 - m);
        salpha[lane] = e0; salpha[lane + 32] = e1;
        float su = e0 + e1;
        #pragma unroll
        for (int o = 16; o > 0; o >>= 1) su += __shfl_xor_sync(0xffffffffu, su, o);
        if (lane == 0) sinv = 1.0f/su;
    }
    __syncthreads();
    float inv = sinv;
    for (int e = tid; e < 1024; e += 512){
        float acc = 0.f;
        #pragma unroll 16
        for (int s = 0; s < 64; s++)
            acc += salpha[s]*src[((size_t)(s*Bb + b))*1024 + e];
        acc *= inv;
        split_store(acc, Yh + b*2048 + 1024 + e, Yl + b*2048 + 1024 + e);
    }
    cudaTriggerProgrammaticLaunchCompletion();
}

// ---------------- 3-pass split-bf16 GEMM (PDL, trigger at end) ----------------
// C[M,N] = A[M,K] * B[N,K]^T  with A ~ Ah+Al, B ~ Bh+Bl (3 mma passes).
// epi: 0=store, 1=store+bias, 2=LSTM cell (interleaved gates), 3=tanh+split
// epi 3 writes bf16 hi/lo to h1h/h1l (X) and fp16 hi/lo to o2h/o2l (AV).
template<int BM, int BN, int BK, int WM, int WN, int STAGES>
__global__ void __launch_bounds__(32*(BM/WM)*(BN/WN))
gemm3(const bf16* __restrict__ Ah, const bf16* __restrict__ Al, int lda,
      const bf16* __restrict__ Bh, const bf16* __restrict__ Bl, int ldb,
      float* __restrict__ C, int ldc,
      int M, int N, int K, int epi,
      const float* __restrict__ addend,
      const float* __restrict__ bias,
      const float* __restrict__ cin, float* __restrict__ cout,
      bf16* __restrict__ h1h, bf16* __restrict__ h1l, int h1ld,
      bf16* __restrict__ h2h, bf16* __restrict__ h2l, int h2ld,
      float* __restrict__ hf32,
      bf16* __restrict__ o2h, bf16* __restrict__ o2l, int o2ld, int o2r0)
{
    constexpr int WARPS_M = BM/WM, WARPS_N = BN/WN;
    constexpr int THREADS = 32*WARPS_M*WARPS_N;
    constexpr int MF = WM/16, NF = WN/8;
    constexpr int BKP = BK + 8;
    constexpr int WRD = BKP/2;
    constexpr int CH  = BK/8;
    constexpr int ASZ = BM*BKP, BSZ = BN*BKP;
    constexpr int STG = 2*ASZ + 2*BSZ;
    extern __shared__ bf16 smem[];

    const int tid = threadIdx.x, wid = tid >> 5, lane = tid & 31;
    const int wm = wid / WARPS_N, wn = wid % WARPS_N;
    const int g = lane >> 2, t = lane & 3;
    const int bm0 = blockIdx.x*BM, bn0 = blockIdx.y*BN;

    float acc[MF][NF][4];
    #pragma unroll
    for (int a = 0; a < MF; a++)
        #pragma unroll
        for (int b = 0; b < NF; b++)
            #pragma unroll
            for (int c = 0; c < 4; c++) acc[a][b][c] = 0.f;

    const int KT = K/BK;

    auto loadB = [&](int kt, int st){
        bf16* s = smem + st*STG;
        int k0 = kt*BK;
        for (int c = tid; c < BN*CH; c += THREADS){
            int r = c/CH, cc = c%CH;
            size_t go = (size_t)(bn0 + r)*ldb + k0 + cc*8;
            cpasync16(s + 2*ASZ + r*BKP + cc*8, Bh + go);
            cpasync16(s + 2*ASZ + BSZ + r*BKP + cc*8, Bl + go);
        }
    };
    auto loadA = [&](int kt, int st){
        bf16* s = smem + st*STG;
        int k0 = kt*BK;
        for (int c = tid; c < BM*CH; c += THREADS){
            int r = c/CH, cc = c%CH;
            size_t go = (size_t)(bm0 + r)*lda + k0 + cc*8;
            cpasync16(s + r*BKP + cc*8, Ah + go);
            cpasync16(s + ASZ + r*BKP + cc*8, Al + go);
        }
    };

    // Weight (B) prefetch overlaps the predecessor tail; sync before touching A.
    #pragma unroll
    for (int s = 0; s < STAGES-1; s++) loadB(s, s);
    cudaGridDependencySynchronize();
    loadA(0, 0); cpcommit();
    #pragma unroll
    for (int s = 1; s < STAGES-1; s++){ loadA(s, s); cpcommit(); }

    for (int kt = 0; kt < KT; kt++){
        cpwait<STAGES-2>();
        __syncthreads();
        int nstage = kt + STAGES - 1;
        if (nstage < KT){ loadB(nstage, nstage % STAGES); loadA(nstage, nstage % STAGES); }
        cpcommit();

        const bf16* s = smem + (kt % STAGES)*STG;
        const uint32_t* sAh = (const uint32_t*)s;
        const uint32_t* sAl = (const uint32_t*)(s + ASZ);
        const uint32_t* sBh = (const uint32_t*)(s + 2*ASZ);
        const uint32_t* sBl = (const uint32_t*)(s + 2*ASZ + BSZ);
        #pragma unroll
        for (int ks = 0; ks < BK/16; ks++){
            uint32_t af[MF][4], alf[MF][4], bhf[NF][2], blf[NF][2];
            #pragma unroll
            for (int mf = 0; mf < MF; mf++){
                int r0 = wm*WM + mf*16;
                int i0 = (r0 + g)*WRD + ks*8 + t;
                int i1 = (r0 + g + 8)*WRD + ks*8 + t;
                af[mf][0] = sAh[i0];   af[mf][1] = sAh[i1];
                af[mf][2] = sAh[i0+4]; af[mf][3] = sAh[i1+4];
                alf[mf][0] = sAl[i0];   alf[mf][1] = sAl[i1];
                alf[mf][2] = sAl[i0+4]; alf[mf][3] = sAl[i1+4];
            }
            #pragma unroll
            for (int nf = 0; nf < NF; nf++){
                int cb = wn*WN + nf*8 + g;
                int i0 = cb*WRD + ks*8 + t;
                bhf[nf][0] = sBh[i0]; bhf[nf][1] = sBh[i0+4];
                blf[nf][0] = sBl[i0]; blf[nf][1] = sBl[i0+4];
            }
            #pragma unroll
            for (int mf = 0; mf < MF; mf++)
                #pragma unroll
                for (int nf = 0; nf < NF; nf++){
                    mma_bf16(acc[mf][nf], af[mf],  bhf[nf]);
                    mma_bf16(acc[mf][nf], alf[mf], bhf[nf]);
                    mma_bf16(acc[mf][nf], af[mf],  blf[nf]);
                }
        }
        __syncthreads();
    }

    // epilogue
    #pragma unroll
    for (int mf = 0; mf < MF; mf++){
        #pragma unroll
        for (int nf = 0; nf < NF; nf++){
            #pragma unroll
            for (int half = 0; half < 2; half++){
                int row = bm0 + wm*WM + mf*16 + g + half*8;
                int col = bn0 + wn*WN + nf*8 + 2*t;
                float v0 = acc[mf][nf][half*2 + 0];
                float v1 = acc[mf][nf][half*2 + 1];
                if (epi <= 1){
                    if (epi == 1){ v0 += bias[col]; v1 += bias[col+1]; }
                    C[(size_t)row*ldc + col]     = v0;
                    C[(size_t)row*ldc + col + 1] = v1;
                } else if (epi == 2){
                    if (addend){ v0 += addend[(size_t)row*N + col];
                                 v1 += addend[(size_t)row*N + col + 1]; }
                    if (bias){ v0 += bias[col]; v1 += bias[col+1]; }
                    float w0 = __shfl_xor_sync(0xffffffffu, v0, 1);
                    float w1 = __shfl_xor_sync(0xffffffffu, v1, 1);
                    if ((t & 1) == 0){
                        // even lanes hold (i,f); partner holds (g,o)
                        float ig = sigmoidf_(v0), fg = sigmoidf_(v1);
                        float gg = tanhf(w0),    og = sigmoidf_(w1);
                        int ch = col >> 2;
                        float cn = fg*cin[row*1024 + ch] + ig*gg;
                        float hn = og*tanhf(cn);
                        cout[row*1024 + ch] = cn;
                        bf16 hh = __float2bfloat16(hn);
                        bf16 hl = __float2bfloat16(hn - __bfloat162float(hh));
                        h1h[row*h1ld + ch] = hh;
                        h1l[row*h1ld + ch] = hl;
                        if (h2h){ h2h[row*h2ld + ch] = hh; h2l[row*h2ld + ch] = hl; }
                        if (hf32) hf32[row*1024 + ch] = hn;
                    }
                } else { // epi == 3 : tanh; bf16 split -> X, fp16 split -> AV
                    float a0 = tanhf(v0), a1 = tanhf(v1);
                    bf16 p0 = __float2bfloat16(a0);
                    bf16 q0 = __float2bfloat16(a0 - __bfloat162float(p0));
                    bf16 p1 = __float2bfloat16(a1);
                    bf16 q1 = __float2bfloat16(a1 - __bfloat162float(p1));
                    h1h[row*h1ld + col]   = p0; h1l[row*h1ld + col]   = q0;
                    h1h[row*h1ld + col+1] = p1; h1l[row*h1ld + col+1] = q1;
                    __half* avh = (__half*)o2h;
                    __half* avl = (__half*)o2l;
                    __half f0 = __float2half(a0);
                    __half e0 = __float2half(a0 - __half2float(f0));
                    __half f1 = __float2half(a1);
                    __half e1 = __float2half(a1 - __half2float(f1));
                    avh[(size_t)(o2r0+row)*o2ld + col]   = f0;
                    avl[(size_t)(o2r0+row)*o2ld + col]   = e0;
                    avh[(size_t)(o2r0+row)*o2ld + col+1] = f1;
                    avl[(size_t)(o2r0+row)*o2ld + col+1] = e1;
                }
            }
        }
    }
    cudaTriggerProgrammaticLaunchCompletion();
}

// ---------------- 2-pass fp16 vocab GEMM: out = AV @ Wout^T -------------------
// C = (Ah+Al) @ Bh^T  (drops A·Bl; fp16 residual ~4e-4 rel, within tolerance).
// BM=128, BN=128, BK=32, WM=64, WN=32, 2 stages — same pipeline as gemm3 large.
__global__ void __launch_bounds__(256)
k_vocab2(const __half* __restrict__ Ah, const __half* __restrict__ Al,
         const __half* __restrict__ Bh, const __half* __restrict__ Bl,
         float* __restrict__ C)
{
    constexpr int BM=128, BN=128, BK=32, STAGES=2;
    constexpr int MF=4, NF=4;
    constexpr int BKP=BK+8, WRD=BKP/2, CH=BK/8;
    constexpr int ASZ=BM*BKP, BSZ=BN*BKP, STG=2*ASZ+2*BSZ;
    extern __shared__ __half hsmem[];

    const int tid = threadIdx.x, wid = tid >> 5, lane = tid & 31;
    const int wm = wid >> 2, wn = wid & 3;   // 2x4 warps, WM=64, WN=32
    const int g = lane >> 2, t = lane & 3;
    const int bm0 = blockIdx.x*BM, bn0 = (int)blockIdx.y*BN;

    float acc[MF][NF][4];
    #pragma unroll
    for (int a = 0; a < MF; a++)
        #pragma unroll
        for (int b = 0; b < NF; b++)
            #pragma unroll
            for (int c = 0; c < 4; c++) acc[a][b][c] = 0.f;

    auto loadB = [&](int kt, int st){
        __half* s = hsmem + st*STG;
        int k0 = kt*BK;
        for (int c = tid; c < BN*CH; c += 256){
            int r = c/CH, cc = c%CH;
            size_t go = (size_t)(bn0 + r)*1024 + k0 + cc*8;
            cpasync16(s + 2*ASZ + r*BKP + cc*8, Bh + go);
            cpasync16(s + 2*ASZ + BSZ + r*BKP + cc*8, Bl + go);
        }
    };
    auto loadA = [&](int kt, int st){
        __half* s = hsmem + st*STG;
        int k0 = kt*BK;
        for (int c = tid; c < BM*CH; c += 256){
            int r = c/CH, cc = c%CH;
            size_t go = (size_t)(bm0 + r)*1024 + k0 + cc*8;
            cpasync16(s + r*BKP + cc*8, Ah + go);
            cpasync16(s + ASZ + r*BKP + cc*8, Al + go);
        }
    };

    loadB(0, 0);
    cudaGridDependencySynchronize();
    loadA(0, 0); cpcommit();

    for (int kt = 0; kt < 32; kt++){
        cpwait<0>();
        __syncthreads();
        if (kt + 1 < 32){ loadB(kt + 1, (kt + 1) & 1); loadA(kt + 1, (kt + 1) & 1); }
        cpcommit();

        const __half* s = hsmem + (kt & 1)*STG;
        const uint32_t* sAh = (const uint32_t*)s;
        const uint32_t* sAl = (const uint32_t*)(s + ASZ);
        const uint32_t* sBh = (const uint32_t*)(s + 2*ASZ);
        #pragma unroll
        for (int ks = 0; ks < 2; ks++){
            uint32_t af[MF][4], alf[MF][4], bhf[NF][2];
            #pragma unroll
            for (int mf = 0; mf < MF; mf++){
                int r0 = wm*64 + mf*16;
                int i0 = (r0 + g)*WRD + ks*8 + t;
                int i1 = (r0 + g + 8)*WRD + ks*8 + t;
                af[mf][0] = sAh[i0];   af[mf][1] = sAh[i1];
                af[mf][2] = sAh[i0+4]; af[mf][3] = sAh[i1+4];
                alf[mf][0] = sAl[i0];   alf[mf][1] = sAl[i1];
                alf[mf][2] = sAl[i0+4]; alf[mf][3] = sAl[i1+4];
            }
            #pragma unroll
            for (int nf = 0; nf < NF; nf++){
                int cb = wn*32 + nf*8 + g;
                int i0 = cb*WRD + ks*8 + t;
                bhf[nf][0] = sBh[i0]; bhf[nf][1] = sBh[i0+4];
            }
            #pragma unroll
            for (int mf = 0; mf < MF; mf++)
                #pragma unroll
                for (int nf = 0; nf < NF; nf++){
                    mma_f16(acc[mf][nf], af[mf],  bhf[nf]);
                    mma_f16(acc[mf][nf], alf[mf], bhf[nf]);
                }
        }
        __syncthreads();
    }

    #pragma unroll
    for (int mf = 0; mf < MF; mf++)
        #pragma unroll
        for (int nf = 0; nf < NF; nf++)
            #pragma unroll
            for (int half = 0; half < 2; half++){
                int row = bm0 + wm*64 + mf*16 + g + half*8;
                int col = bn0 + wn*32 + nf*8 + 2*t;
                C[(size_t)row*32000 + col]     = acc[mf][nf][half*2 + 0];
                C[(size_t)row*32000 + col + 1] = acc[mf][nf][half*2 + 1];
            }
}

// ---------------- host launch ----------------
static constexpr int SM_L = 2*(2*128+2*128)*(32+8)*2;    // 81920 (2 blocks/SM)
static constexpr int SM_G = 3*(2*32+2*32)*(256+8)*2;     // 202752 (BK=256 gates)
static constexpr int SM_C = 3*(2*32+2*16)*(256+8)*2;     // 152064 (BK=256 combine)

template<typename F, typename... Args>
static void launch_pdl(F f, dim3 g, dim3 b, size_t sm, Args... args){
    cudaLaunchConfig_t cfg = {};
    cfg.gridDim = g; cfg.blockDim = b; cfg.dynamicSmemBytes = sm; cfg.stream = 0;
    cudaLaunchAttribute at[1];
    at[0].id = cudaLaunchAttributeProgrammaticStreamSerialization;
    at[0].val.programmaticStreamSerializationAllowed = 1;
    cfg.attrs = at; cfg.numAttrs = 1;
    cudaLaunchKernelEx(&cfg, f, args...);
}

extern "C" void kernel_launch(void* const* d_in, const int* in_sizes, int n_in,
                              void* d_out, int out_size){
    const float* src   = (const float*)d_in[0];
    const float* h0    = (const float*)d_in[1];
    const float* c0    = (const float*)d_in[2];
    const float* emb   = (const float*)d_in[3];
    const float* Wproj = (const float*)d_in[4];
    const float* Wcomb = (const float*)d_in[5];
    const float* Wout  = (const float*)d_in[6];
    const float* Wih0  = (const float*)d_in[7];
    const float* Whh0  = (const float*)d_in[8];
    const float* bih0  = (const float*)d_in[9];
    const float* bhh0  = (const float*)d_in[10];
    const float* Wih1  = (const float*)d_in[11];
    const float* Whh1  = (const float*)d_in[12];
    const float* bih1  = (const float*)d_in[13];
    const float* bhh1  = (const float*)d_in[14];
    const int*   tgt   = (const int*)d_in[15];
    float* out = (float*)d_out;

    void* basep = nullptr;
    cudaGetSymbolAddress(&basep, g_scratch);
    unsigned char* base = (unsigned char*)basep;

    bf16*   encH   = (bf16*)(base + O_ENC_H);
    bf16*   encL   = (bf16*)(base + O_ENC_L);
    float*  attnS  = (float*)(base + O_ATTNS);
    bf16*   WprojH = (bf16*)(base + O_WPROJ_H);
    bf16*   WprojL = (bf16*)(base + O_WPROJ_L);
    bf16*   WwordH = (bf16*)(base + O_WWORD_H);
    bf16*   WwordL = (bf16*)(base + O_WWORD_L);
    bf16*   WcatH  = (bf16*)(base + O_WCAT_H);
    bf16*   WcatL  = (bf16*)(base + O_WCAT_L);
    bf16*   W1H    = (bf16*)(base + O_W1_H);
    bf16*   W1L    = (bf16*)(base + O_W1_L);
    bf16*   WcombH = (bf16*)(base + O_WCOMB_H);
    bf16*   WcombL = (bf16*)(base + O_WCOMB_L);
    __half* WoutH  = (__half*)(base + O_WOUT_H);
    __half* WoutL  = (__half*)(base + O_WOUT_L);
    float*  bias0  = (float*)(base + O_BIAS0);
    float*  bias1  = (float*)(base + O_BIAS1);
    bf16*   AembH  = (bf16*)(base + O_AEMB_H);
    bf16*   AembL  = (bf16*)(base + O_AEMB_L);
    float*  Gword  = (float*)(base + O_GWORD);
    bf16*   XH     = (bf16*)(base + O_X_H);
    bf16*   XL     = (bf16*)(base + O_X_L);
    bf16*   YH     = (bf16*)(base + O_Y_H);
    bf16*   YL     = (bf16*)(base + O_Y_L);
    bf16*   HmidH  = (bf16*)(base + O_HMID_H);
    bf16*   HmidL  = (bf16*)(base + O_HMID_L);
    float*  hf32   = (float*)(base + O_HF32);
    float*  cprev  = (float*)(base + O_CPREV);
    float*  cmid   = (float*)(base + O_CMID);
    __half* AVH    = (__half*)(base + O_AV_H);
    __half* AVL    = (__half*)(base + O_AV_L);

    cudaFuncSetAttribute((const void*)gemm3<128,128,32,64,32,2>,
                         cudaFuncAttributeMaxDynamicSharedMemorySize, SM_L);
    cudaFuncSetAttribute((const void*)gemm3<32,32,256,16,8,3>,
                         cudaFuncAttributeMaxDynamicSharedMemorySize, SM_G);
    cudaFuncSetAttribute((const void*)gemm3<32,16,256,16,8,3>,
                         cudaFuncAttributeMaxDynamicSharedMemorySize, SM_C);
    cudaFuncSetAttribute((const void*)k_vocab2,
                         cudaFuncAttributeMaxDynamicSharedMemorySize, SM_L);

    // ---- setup (vectorized splits/builders) ----
    k_split_enc4<<<2048,256>>>((const float4*)src, (__nv_bfloat162*)encH,
                               (__nv_bfloat162*)encL);
    k_split_plain4<<<2048,256>>>((const float4*)Wproj, (__nv_bfloat162*)WprojH,
                                 (__nv_bfloat162*)WprojL, (size_t)1024*1024/4);
    k_split_plain4<<<4096,256>>>((const float4*)Wcomb, (__nv_bfloat162*)WcombH,
                                 (__nv_bfloat162*)WcombL, (size_t)1024*2048/4);
    k_split_plain4h<<<8192,256>>>((const float4*)Wout, (__half2*)WoutH,
                                  (__half2*)WoutL, (size_t)32000*1024/4);
    k_build_wword4<<<2048,256>>>((const float4*)Wih0, (__nv_bfloat162*)WwordH,
                                 (__nv_bfloat162*)WwordL);
    k_build_wcat4<<<4096,256>>>((const float4*)Wih0, (const float4*)Whh0,
                                (__nv_bfloat162*)WcatH, (__nv_bfloat162*)WcatL);
    k_build_w1_4<<<2048,256>>>((const float4*)Wih1, (const float4*)Whh1,
                               (__nv_bfloat162*)W1H, (__nv_bfloat162*)W1L);
    k_build_bias<<<16,256>>>(bih0, bhh0, bih1, bhh1, bias0, bias1);
    k_gather_emb4<<<1024,256>>>((const float4*)emb, tgt,
                                (__nv_bfloat162*)AembH, (__nv_bfloat162*)AembL);
    k_init_state<<<128,256>>>(h0, c0, cprev, XH, XL);

    // attn_scores = enc @ Wproj^T : [2048,1024]
    launch_pdl(gemm3<128,128,32,64,32,2>, dim3(16,8), dim3(256), (size_t)SM_L,
        (const bf16*)encH, (const bf16*)encL, 1024,
        (const bf16*)WprojH, (const bf16*)WprojL, 1024,
        attnS, 1024, 2048, 1024, 1024, 0,
        (const float*)nullptr, (const float*)nullptr,
        (const float*)nullptr, (float*)nullptr,
        (bf16*)nullptr, (bf16*)nullptr, 0,
        (bf16*)nullptr, (bf16*)nullptr, 0, (float*)nullptr,
        (bf16*)nullptr, (bf16*)nullptr, 0, 0);

    // G_word = emb_gathered @ Wword^T + bias0 : [1536,4096] (permuted gates)
    launch_pdl(gemm3<128,128,32,64,32,2>, dim3(12,32), dim3(256), (size_t)SM_L,
        (const bf16*)AembH, (const bf16*)AembL, 512,
        (const bf16*)WwordH, (const bf16*)WwordL, 512,
        Gword, 4096, 1536, 4096, 512, 1,
        (const float*)nullptr, (const float*)bias0,
        (const float*)nullptr, (float*)nullptr,
        (bf16*)nullptr, (bf16*)nullptr, 0,
        (bf16*)nullptr, (bf16*)nullptr, 0, (float*)nullptr,
        (bf16*)nullptr, (bf16*)nullptr, 0, 0);

    // ---- sequential decode loop: 4 kernels per step (BK=256 loop GEMMs) ----
    for (int t = 0; t < Tt; t++){
        launch_pdl(gemm3<32,32,256,16,8,3>, dim3(1,128), dim3(256), (size_t)SM_G,
            (const bf16*)XH, (const bf16*)XL, 2048,
            (const bf16*)WcatH, (const bf16*)WcatL, 2048,
            (float*)nullptr, 0, 32, 4096, 2048, 2,
            (const float*)(Gword + (size_t)t*32*4096), (const float*)nullptr,
            (const float*)cprev, cmid,
            HmidH, HmidL, 1024,
            (bf16*)nullptr, (bf16*)nullptr, 0, (float*)nullptr,
            (bf16*)nullptr, (bf16*)nullptr, 0, 0);

        launch_pdl(gemm3<32,32,256,16,8,3>, dim3(1,128), dim3(256), (size_t)SM_G,
            (const bf16*)HmidH, (const bf16*)HmidL, 1024,
            (const bf16*)W1H, (const bf16*)W1L, 1024,
            (float*)nullptr, 0, 32, 4096, 1024, 2,
            (const float*)nullptr, (const float*)bias1,
            (const float*)cmid, cprev,
            YH, YL, 2048,
            XH + 1024, XL + 1024, 2048, hf32,
            (bf16*)nullptr, (bf16*)nullptr, 0, 0);

        {
            cudaLaunchConfig_t cfg = {};
            cfg.gridDim = dim3(32); cfg.blockDim = dim3(512);
            cfg.dynamicSmemBytes = 0; cfg.stream = 0;
            cudaLaunchAttribute at[1];
            at[0].id = cudaLaunchAttributeProgrammaticStreamSerialization;
            at[0].val.programmaticStreamSerializationAllowed = 1;
            cfg.attrs = at; cfg.numAttrs = 1;
            cudaLaunchKernelEx(&cfg, k_attention,
                (const float*)attnS, (const float*)hf32, src, YH, YL);
        }

        // combine: av = tanh([h|ctx] @ Wcomb^T) -> X[:,0:1024] (bf16) + AV[t] (fp16)
        launch_pdl(gemm3<32,16,256,16,8,3>, dim3(1,64), dim3(128), (size_t)SM_C,
            (const bf16*)YH, (const bf16*)YL, 2048,
            (const bf16*)WcombH, (const bf16*)WcombL, 2048,
            (float*)nullptr, 0, 32, 1024, 2048, 3,
            (const float*)nullptr, (const float*)nullptr,
            (const float*)nullptr, (float*)nullptr,
            XH, XL, 2048,
            (bf16*)nullptr, (bf16*)nullptr, 0, (float*)nullptr,
            (bf16*)AVH, (bf16*)AVL, 1024, t*32);
    }

    // ---- final vocab projection (fp16 2-pass): scores = AV @ Wout^T ----
    launch_pdl(k_vocab2, dim3(12,250), dim3(256), (size_t)SM_L,
        (const __half*)AVH, (const __half*)AVL,
        (const __half*)WoutH, (const __half*)WoutL, out);
}